// round 12
// baseline (speedup 1.0000x reference)
#include <cuda_runtime.h>
#include <cuda_bf16.h>
#include <cstdint>

// ---------------------------------------------------------------------------
// LSTM T=512, B=64, IN=512, H=1024.
// Phase 1 (HMMA bf16 3-term split): gx[t][cta][b][vn] = x_t @ Wx + bias.
// Phase 2 (persistent, 128 CTAs x 512 thr): R9 kernel body with the global
//   step barrier replaced by per-chunk producer counters:
//   chunk c of A (h cols [64c,64c+64)) is produced by CTAs 8c..8c+7; each
//   CTA arrives on g_cnt[bx>>3] after writing h; consumers wait
//   g_cnt[c] >= 8t just before staging chunk c (rides the existing sync).
//   h double-buffered by t parity (WAR-free by the consume-all argument).
// ---------------------------------------------------------------------------

static constexpr int kT  = 512;
static constexpr int kB  = 64;
static constexpr int kIN = 512;
static constexpr int kH  = 1024;
static constexpr int kBH = kB * kH;
static constexpr int NBLK = 128;

__device__ float g_gx2[(size_t)kT * NBLK * kB * 32];      // [t][cta][b][vn]
__device__ __nv_bfloat16 g_whi2[(size_t)NBLK * 32768];    // per-CTA Wh hi [n=32][k=1024]
__device__ __nv_bfloat16 g_wlo2[(size_t)NBLK * 32768];    // per-CTA Wh lo
__device__ __nv_bfloat16 g_hhi[2 * kBH];                  // h bf16 hi, double-buffered
__device__ __nv_bfloat16 g_hlo[2 * kBH];                  // h bf16 lo
__device__ __nv_bfloat16 g_xhi[(size_t)kT * kB * kIN];    // x hi [m][k]
__device__ __nv_bfloat16 g_xlo[(size_t)kT * kB * kIN];    // x lo
__device__ __nv_bfloat16 g_wxhi[(size_t)4096 * kIN];      // Wx hi [n=4096][k=512]
__device__ __nv_bfloat16 g_wxlo[(size_t)4096 * kIN];      // Wx lo
__device__ unsigned g_bar;
__device__ unsigned g_cnt[16];                            // per-chunk producer counters

__device__ __forceinline__ uint32_t smem_u32(const void* p) {
    uint32_t a;
    asm("{ .reg .u64 t; cvta.to.shared.u64 t, %1; cvt.u32.u64 %0, t; }"
        : "=r"(a) : "l"(p));
    return a;
}
__device__ __forceinline__ void ldsm_x4(uint32_t* r, uint32_t addr) {
    asm volatile("ldmatrix.sync.aligned.m8n8.x4.shared.b16 {%0,%1,%2,%3}, [%4];"
                 : "=r"(r[0]), "=r"(r[1]), "=r"(r[2]), "=r"(r[3]) : "r"(addr));
}
__device__ __forceinline__ void mma_bf16(float* c, const uint32_t* a,
                                         uint32_t b0, uint32_t b1) {
    asm volatile(
        "mma.sync.aligned.m16n8k16.row.col.f32.bf16.bf16.f32 "
        "{%0,%1,%2,%3}, {%4,%5,%6,%7}, {%8,%9}, {%0,%1,%2,%3};"
        : "+f"(c[0]), "+f"(c[1]), "+f"(c[2]), "+f"(c[3])
        : "r"(a[0]), "r"(a[1]), "r"(a[2]), "r"(a[3]), "r"(b0), "r"(b1));
}
__device__ __forceinline__ void cp16(uint32_t dst, const void* src) {
    asm volatile("cp.async.cg.shared.global [%0], [%1], 16;"
                 :: "r"(dst), "l"(src) : "memory");
}
__device__ __forceinline__ void cp_commit() {
    asm volatile("cp.async.commit_group;" ::: "memory");
}
__device__ __forceinline__ void cp_wait1() {
    asm volatile("cp.async.wait_group 1;" ::: "memory");
}
__device__ __forceinline__ void cp_wait0() {
    asm volatile("cp.async.wait_group 0;" ::: "memory");
}
__device__ __forceinline__ float sigmoidf_(float x) {
    return 1.0f / (1.0f + __expf(-x));
}
__device__ __forceinline__ void bar_arrive_release(unsigned* p) {
    asm volatile("red.release.gpu.global.add.u32 [%0], 1;" :: "l"(p) : "memory");
}
__device__ __forceinline__ unsigned ld_acquire(unsigned* p) {
    unsigned v;
    asm volatile("ld.acquire.gpu.global.u32 %0, [%1];" : "=r"(v) : "l"(p) : "memory");
    return v;
}

__global__ void reset_kernel() {
    g_bar = 0u;
    for (int i = 0; i < 16; i++) g_cnt[i] = 0u;
}

// ---------------------------------------------------------------------------
// Prep kernels: fp32 -> bf16 hi/lo
// ---------------------------------------------------------------------------
__device__ __forceinline__ void split_bf16(float v, __nv_bfloat16& hi, __nv_bfloat16& lo) {
    hi = __float2bfloat16_rn(v);
    lo = __float2bfloat16_rn(v - __bfloat162float(hi));
}

__global__ void __launch_bounds__(256) prep_x(const float* __restrict__ x) {
    size_t i = (size_t)blockIdx.x * 256 + threadIdx.x;
    __nv_bfloat16 hi, lo;
    split_bf16(x[i], hi, lo);
    g_xhi[i] = hi; g_xlo[i] = lo;
}

__global__ void __launch_bounds__(256) prep_wx(
    const float* __restrict__ Wf, const float* __restrict__ Wi,
    const float* __restrict__ Wc, const float* __restrict__ Wo)
{
    size_t i = (size_t)blockIdx.x * 256 + threadIdx.x;   // 4096*512 total
    int n = (int)(i >> 9), k = (int)(i & 511);
    int gate = n >> 10, h = n & 1023;
    const float* W = (gate == 0) ? Wf : (gate == 1) ? Wi : (gate == 2) ? Wc : Wo;
    __nv_bfloat16 hi, lo;
    split_bf16(W[(size_t)(kH + k) * kH + h], hi, lo);
    g_wxhi[i] = hi; g_wxlo[i] = lo;
}

__global__ void __launch_bounds__(256) prep_weights(
    const float* __restrict__ Wf, const float* __restrict__ Wi,
    const float* __restrict__ Wc, const float* __restrict__ Wo)
{
    const int cta = blockIdx.x;
    const int n0h = cta * 8;
    for (int g = 0; g < 4; g++) {
        const float* W = (g == 0) ? Wf : (g == 1) ? Wi : (g == 2) ? Wc : Wo;
        for (int idx = threadIdx.x; idx < 8 * kH; idx += 256) {
            int col = idx & 7, r = idx >> 3;
            __nv_bfloat16 hi, lo;
            split_bf16(W[(size_t)r * kH + n0h + col], hi, lo);
            size_t o = (size_t)cta * 32768 + (size_t)(g * 8 + col) * kH + r;
            g_whi2[o] = hi;
            g_wlo2[o] = lo;
        }
    }
}

// ---------------------------------------------------------------------------
// Phase 1 HMMA: gx = X @ Wx + b.  M=32768, N=4096, K=512. (proven R9)
// ---------------------------------------------------------------------------
static constexpr uint32_t P1_AB = 18432;   // 128 rows * 144 B
static constexpr uint32_t P1_OFFB = 4 * P1_AB;          // 73728
static constexpr uint32_t P1_SM = 8 * P1_AB;            // 147456

__global__ void __launch_bounds__(512, 1) phase1_hmma(
    const float* __restrict__ bf, const float* __restrict__ bi,
    const float* __restrict__ bc, const float* __restrict__ bo)
{
    extern __shared__ __align__(128) char smem[];
    const uint32_t sb = smem_u32(smem);
    const int tid  = threadIdx.x;
    const int wid  = tid >> 5;
    const int lane = tid & 31;
    const int mi2  = wid & 3;
    const int nw   = wid >> 2;
    const int n0   = blockIdx.x * 128;
    const int m0   = blockIdx.y * 128;
    const int gate = n0 >> 10;
    const float* biasg = (gate == 0) ? bf : (gate == 1) ? bi : (gate == 2) ? bc : bo;

    const int s_row0 = tid >> 3, s_c16 = tid & 7;
    const int s_row1 = (tid + 512) >> 3;
    const uint32_t so0 = (uint32_t)(s_row0 * 144 + s_c16 * 16);
    const uint32_t so1 = (uint32_t)(s_row1 * 144 + s_c16 * 16);

    auto stage = [&](int c) {
        const int buf = c & 1;
        const uint32_t ahi = sb + buf * 2 * P1_AB;
        const uint32_t alo = ahi + P1_AB;
        const uint32_t bhi = sb + P1_OFFB + buf * 2 * P1_AB;
        const uint32_t blo = bhi + P1_AB;
        const size_t ga0 = (size_t)(m0 + s_row0) * kIN + c * 64 + s_c16 * 8;
        const size_t ga1 = (size_t)(m0 + s_row1) * kIN + c * 64 + s_c16 * 8;
        const size_t gb0 = (size_t)(n0 + s_row0) * kIN + c * 64 + s_c16 * 8;
        const size_t gb1 = (size_t)(n0 + s_row1) * kIN + c * 64 + s_c16 * 8;
        cp16(ahi + so0, &g_xhi[ga0]);  cp16(ahi + so1, &g_xhi[ga1]);
        cp16(alo + so0, &g_xlo[ga0]);  cp16(alo + so1, &g_xlo[ga1]);
        cp16(bhi + so0, &g_wxhi[gb0]); cp16(bhi + so1, &g_wxhi[gb1]);
        cp16(blo + so0, &g_wxlo[gb0]); cp16(blo + so1, &g_wxlo[gb1]);
    };

    uint32_t aoff[2];
#pragma unroll
    for (int i = 0; i < 2; i++)
        aoff[i] = (uint32_t)((32 * mi2 + 16 * i + (lane & 15)) * 144 + (lane >> 4) * 16);
    uint32_t boff[2];
#pragma unroll
    for (int j = 0; j < 2; j++)
        boff[j] = (uint32_t)((32 * nw + 16 * j + (lane & 7) + ((lane >> 4) << 3)) * 144
                             + ((lane >> 3) & 1) * 16);

    float C[2][2][2][4];
#pragma unroll
    for (int i = 0; i < 2; i++)
#pragma unroll
        for (int j = 0; j < 2; j++)
#pragma unroll
            for (int h2 = 0; h2 < 2; h2++)
#pragma unroll
                for (int q = 0; q < 4; q++) C[i][j][h2][q] = 0.0f;

    stage(0); cp_commit();

    for (int c = 0; c < 8; ++c) {
        if (c + 1 < 8) stage(c + 1);
        cp_commit();
        if (c + 1 < 8) cp_wait1(); else cp_wait0();
        __syncthreads();
        const int buf = c & 1;
        const uint32_t ahi = sb + buf * 2 * P1_AB;
        const uint32_t alo = ahi + P1_AB;
        const uint32_t bhi = sb + P1_OFFB + buf * 2 * P1_AB;
        const uint32_t blo = bhi + P1_AB;
#pragma unroll
        for (int u = 0; u < 4; ++u) {
            uint32_t ah[2][4], al[2][4], bh[2][4], bl[2][4];
#pragma unroll
            for (int i = 0; i < 2; i++) {
                ldsm_x4(ah[i], ahi + aoff[i] + u * 32);
                ldsm_x4(al[i], alo + aoff[i] + u * 32);
            }
#pragma unroll
            for (int j = 0; j < 2; j++) {
                ldsm_x4(bh[j], bhi + boff[j] + u * 32);
                ldsm_x4(bl[j], blo + boff[j] + u * 32);
            }
#pragma unroll
            for (int i = 0; i < 2; i++)
#pragma unroll
                for (int j = 0; j < 2; j++) {
                    mma_bf16(C[i][j][0], ah[i], bh[j][0], bh[j][1]);
                    mma_bf16(C[i][j][1], ah[i], bh[j][2], bh[j][3]);
                    mma_bf16(C[i][j][0], ah[i], bl[j][0], bl[j][1]);
                    mma_bf16(C[i][j][1], ah[i], bl[j][2], bl[j][3]);
                    mma_bf16(C[i][j][0], al[i], bh[j][0], bh[j][1]);
                    mma_bf16(C[i][j][1], al[i], bh[j][2], bh[j][3]);
                }
        }
        __syncthreads();
    }

    // epilogue: bias + scattered gx2 stores (float2, even offsets)
#pragma unroll
    for (int j = 0; j < 2; j++)
#pragma unroll
        for (int h2 = 0; h2 < 2; h2++) {
            const int col = 32 * nw + 16 * j + 8 * h2 + (lane & 3) * 2;
            const int n = n0 + col;
            const int hh = n & 1023;
            const int cta = hh >> 3, jj = hh & 7;
            const float b0 = biasg[hh], b1 = biasg[hh + 1];
#pragma unroll
            for (int i = 0; i < 2; i++)
#pragma unroll
                for (int rr = 0; rr < 2; rr++) {
                    const int r = 32 * mi2 + 16 * i + (lane >> 2) + 8 * rr;
                    const int m = m0 + r;
                    const int t = m >> 6, b = m & 63;
                    float2 v;
                    v.x = C[i][j][h2][2 * rr]     + b0;
                    v.y = C[i][j][h2][2 * rr + 1] + b1;
                    *reinterpret_cast<float2*>(
                        &g_gx2[(((size_t)t * NBLK + cta) * kB + b) * 32 + gate * 8 + jj]) = v;
                }
        }
}

// ---------------------------------------------------------------------------
// Persistent HMMA phase 2, v6 = R9 body + per-chunk dataflow sync.
// 128 CTAs x 512 threads. Warp w: mi = w&3 (m16), ks = w>>2 (k16/chunk).
// ---------------------------------------------------------------------------
static constexpr uint32_t SB_STRIDE = 2064;
static constexpr uint32_t OFF_BHI = 0;
static constexpr uint32_t OFF_BLO = 32 * SB_STRIDE;              // 66048
static constexpr uint32_t OFF_A   = 2 * 32 * SB_STRIDE;          // 132096
static constexpr uint32_t ABUF    = 9216;                        // 64 * 144
static constexpr int      PRE_STRIDE = 34;                       // floats (even)
static constexpr int      PRE_FLOATS = 64 * PRE_STRIDE;          // 2176
static constexpr uint32_t OFF_PRE = OFF_A + 3 * 2 * ABUF;        // 187392
static constexpr uint32_t SM_TOTAL2 = OFF_PRE + 4 * PRE_FLOATS * 4;  // 222208

__global__ void __launch_bounds__(512, 1) lstm_hmma6(float* __restrict__ out)
{
    extern __shared__ __align__(128) char smem[];
    const uint32_t sb = smem_u32(smem);

    const int tid  = threadIdx.x;
    const int wid  = tid >> 5;
    const int lane = tid & 31;
    const int bx   = blockIdx.x;
    const int n0h  = bx * 8;
    const int mi   = wid & 3;
    const int ks   = wid >> 2;
    const int grp  = bx >> 3;          // this CTA's producer group (chunk index)

    // resident weights
    {
        const uint4* shi = reinterpret_cast<const uint4*>(&g_whi2[(size_t)bx * 32768]);
        const uint4* slo = reinterpret_cast<const uint4*>(&g_wlo2[(size_t)bx * 32768]);
        for (int i = tid; i < 4096; i += 512) {
            int n = i >> 7, c8 = i & 127;
            uint32_t o = n * SB_STRIDE + c8 * 16;
            *reinterpret_cast<uint4*>(smem + OFF_BHI + o) = shi[i];
            *reinterpret_cast<uint4*>(smem + OFF_BLO + o) = slo[i];
        }
    }
    // zero BOTH h buffers (this CTA's linear slice of each)
    g_hhi[bx * 512 + tid] = __float2bfloat16(0.0f);
    g_hlo[bx * 512 + tid] = __float2bfloat16(0.0f);
    g_hhi[kBH + bx * 512 + tid] = __float2bfloat16(0.0f);
    g_hlo[kBH + bx * 512 + tid] = __float2bfloat16(0.0f);
    __syncthreads();
    if (tid == 0) {
        bar_arrive_release(&g_bar);
        while (ld_acquire(&g_bar) < NBLK) { }
    }
    __syncthreads();

    // fragment bases (R9 mappings)
    const uint32_t a_off = (uint32_t)((16 * mi + (lane & 15)) * 144
                                      + (lane >> 4) * 16 + ks * 32);
    uint32_t bHi[2], bLo[2];
#pragma unroll
    for (int j = 0; j < 2; j++) {
        const uint32_t b_row = 16 * j + (lane & 7) + ((lane >> 4) << 3);
        bHi[j] = sb + OFF_BHI + b_row * SB_STRIDE + ((lane >> 3) & 1) * 16;
        bLo[j] = sb + OFF_BLO + b_row * SB_STRIDE + ((lane >> 3) & 1) * 16;
    }

    // staging: ONE 16B slot per thread per array (64 rows x 8 uint4)
    const int s_row0 = tid >> 3, s_c16 = tid & 7;
    const uint32_t so0 = (uint32_t)(s_row0 * 144 + s_c16 * 16);

    // gate-update mapping
    const int ub = tid >> 3, uj = tid & 7;
    float* pre0 = reinterpret_cast<float*>(smem + OFF_PRE);
    float* pre1 = pre0 + PRE_FLOATS;
    float* pre2 = pre1 + PRE_FLOATS;
    float* pre3 = pre2 + PRE_FLOATS;
    float* preK = pre0 + ks * PRE_FLOATS;

    float c_reg = 0.0f;

    float gx4[4];
    {
        const float* gx = &g_gx2[(((size_t)0 * NBLK + bx) * kB + ub) * 32];
#pragma unroll
        for (int g = 0; g < 4; ++g) gx4[g] = gx[8 * g + uj];
    }

    for (int t = 0; t < kT; ++t) {
        const __nv_bfloat16* hhr = g_hhi + (size_t)((t + 1) & 1) * kBH;  // h_{t-1}
        const __nv_bfloat16* hlr = g_hlo + (size_t)((t + 1) & 1) * kBH;
        const unsigned need = (unsigned)(8 * t);

        auto stageA = [&](int c) {
            const int buf = c % 3;
            const uint32_t ahi = sb + OFF_A + buf * 2 * ABUF;
            const uint32_t alo = ahi + ABUF;
            const size_t g0 = (size_t)s_row0 * kH + c * 64 + s_c16 * 8;
            cp16(ahi + so0, &hhr[g0]);
            cp16(alo + so0, &hlr[g0]);
        };

        float C00[4] = {0,0,0,0}, C01[4] = {0,0,0,0};
        float C10[4] = {0,0,0,0}, C11[4] = {0,0,0,0};

        // prologue: wait for producers of chunks 0,1 then stage them
        if (tid == 0) {
            while (ld_acquire(&g_cnt[0]) < need) { __nanosleep(32); }
            while (ld_acquire(&g_cnt[1]) < need) { __nanosleep(32); }
        }
        __syncthreads();
        stageA(0); cp_commit();
        stageA(1); cp_commit();

        for (int c = 0; c < 16; ++c) {
            cp_wait1();
            if (tid == 0 && c + 2 < 16) {
                while (ld_acquire(&g_cnt[c + 2]) < need) { __nanosleep(32); }
            }
            __syncthreads();
            if (c + 2 < 16) stageA(c + 2);
            cp_commit();

            const int buf = c % 3;
            const uint32_t ahi = sb + OFF_A + buf * 2 * ABUF;
            const uint32_t alo = ahi + ABUF;
            uint32_t ah[4], al[4], bh0[4], bh1[4], bl0[4], bl1[4];
            ldsm_x4(ah, ahi + a_off);
            ldsm_x4(al, alo + a_off);
            const uint32_t bo = (uint32_t)(c * 128 + ks * 32);
            ldsm_x4(bh0, bHi[0] + bo);
            ldsm_x4(bh1, bHi[1] + bo);
            ldsm_x4(bl0, bLo[0] + bo);
            ldsm_x4(bl1, bLo[1] + bo);
            mma_bf16(C00, ah, bh0[0], bh0[1]); mma_bf16(C01, ah, bh0[2], bh0[3]);
            mma_bf16(C10, ah, bh1[0], bh1[1]); mma_bf16(C11, ah, bh1[2], bh1[3]);
            mma_bf16(C00, ah, bl0[0], bl0[1]); mma_bf16(C01, ah, bl0[2], bl0[3]);
            mma_bf16(C10, ah, bl1[0], bl1[1]); mma_bf16(C11, ah, bl1[2], bl1[3]);
            mma_bf16(C00, al, bh0[0], bh0[1]); mma_bf16(C01, al, bh0[2], bh0[3]);
            mma_bf16(C10, al, bh1[0], bh1[1]); mma_bf16(C11, al, bh1[2], bh1[3]);
        }

        // publish partials into pre[ks] (stride 34 -> float2 stores aligned)
        {
            const int r0 = 16 * mi + (lane >> 2);
            const int cb = (lane & 3) * 2;
            float2 v;
            v.x = C00[0]; v.y = C00[1];
            *reinterpret_cast<float2*>(&preK[r0 * PRE_STRIDE + cb]) = v;
            v.x = C00[2]; v.y = C00[3];
            *reinterpret_cast<float2*>(&preK[(r0 + 8) * PRE_STRIDE + cb]) = v;
            v.x = C01[0]; v.y = C01[1];
            *reinterpret_cast<float2*>(&preK[r0 * PRE_STRIDE + cb + 8]) = v;
            v.x = C01[2]; v.y = C01[3];
            *reinterpret_cast<float2*>(&preK[(r0 + 8) * PRE_STRIDE + cb + 8]) = v;
            v.x = C10[0]; v.y = C10[1];
            *reinterpret_cast<float2*>(&preK[r0 * PRE_STRIDE + cb + 16]) = v;
            v.x = C10[2]; v.y = C10[3];
            *reinterpret_cast<float2*>(&preK[(r0 + 8) * PRE_STRIDE + cb + 16]) = v;
            v.x = C11[0]; v.y = C11[1];
            *reinterpret_cast<float2*>(&preK[r0 * PRE_STRIDE + cb + 24]) = v;
            v.x = C11[2]; v.y = C11[3];
            *reinterpret_cast<float2*>(&preK[(r0 + 8) * PRE_STRIDE + cb + 24]) = v;
        }
        __syncthreads();

        // gate math + c/h update (1 item/thread); write h into buf[t&1]
        {
            const int b = ub, j = uj;
            const int o0 = b * PRE_STRIDE + j;
            float pf = pre0[o0]      + pre1[o0]      + pre2[o0]      + pre3[o0]      + gx4[0];
            float pi = pre0[o0 + 8]  + pre1[o0 + 8]  + pre2[o0 + 8]  + pre3[o0 + 8]  + gx4[1];
            float pg = pre0[o0 + 16] + pre1[o0 + 16] + pre2[o0 + 16] + pre3[o0 + 16] + gx4[2];
            float po = pre0[o0 + 24] + pre1[o0 + 24] + pre2[o0 + 24] + pre3[o0 + 24] + gx4[3];
            float f  = sigmoidf_(pf);
            float ii = sigmoidf_(pi);
            float gg = tanhf(pg);
            float oo = sigmoidf_(po);
            float cn = f * c_reg + ii * gg;
            c_reg = cn;
            float h = oo * tanhf(cn);
            out[(size_t)t * kBH + (size_t)b * kH + n0h + j] = h;
            __nv_bfloat16 bh16, bl16;
            split_bf16(h, bh16, bl16);
            const size_t wb = (size_t)(t & 1) * kBH + (size_t)b * kH + n0h + j;
            g_hhi[wb] = bh16;
            g_hlo[wb] = bl16;
            if (t == kT - 1) {
                out[(size_t)kT * kBH + (size_t)b * kH + n0h + j] = h;
                out[(size_t)kT * kBH + kBH + (size_t)b * kH + n0h + j] = cn;
            }
        }

        // arrival on this CTA's producer counter (no global wait)
        if (t < kT - 1) {
            __syncthreads();                 // all h writes of this CTA done
            if (tid == 0) bar_arrive_release(&g_cnt[grp]);
            // prefetch next step's gx (overlaps other CTAs' progress)
            const float* gx = &g_gx2[(((size_t)(t + 1) * NBLK + bx) * kB + ub) * 32];
#pragma unroll
            for (int g = 0; g < 4; ++g) gx4[g] = gx[8 * g + uj];
        }
    }
}

// ---------------------------------------------------------------------------
extern "C" void kernel_launch(void* const* d_in, const int* in_sizes, int n_in,
                              void* d_out, int out_size)
{
    const float* x  = (const float*)d_in[0];
    const float* Wf = (const float*)d_in[1];
    const float* bf = (const float*)d_in[2];
    const float* Wi = (const float*)d_in[3];
    const float* bi = (const float*)d_in[4];
    const float* Wc = (const float*)d_in[5];
    const float* bc = (const float*)d_in[6];
    const float* Wo = (const float*)d_in[7];
    const float* bo = (const float*)d_in[8];
    float* out = (float*)d_out;

    cudaFuncSetAttribute(phase1_hmma,
                         cudaFuncAttributeMaxDynamicSharedMemorySize, P1_SM);
    cudaFuncSetAttribute(lstm_hmma6,
                         cudaFuncAttributeMaxDynamicSharedMemorySize, SM_TOTAL2);

    reset_kernel<<<1, 1>>>();
    prep_x<<<(kT * kB * kIN) / 256, 256>>>(x);
    prep_wx<<<(4096 * kIN) / 256, 256>>>(Wf, Wi, Wc, Wo);
    prep_weights<<<NBLK, 256>>>(Wf, Wi, Wc, Wo);

    dim3 g1(4096 / 128, (kT * kB) / 128);   // 32 x 256
    phase1_hmma<<<g1, 512, P1_SM>>>(bf, bi, bc, bo);

    lstm_hmma6<<<NBLK, 512, SM_TOTAL2>>>(out);
}

// round 13
// speedup vs baseline: 1.6480x; 1.6480x over previous
#include <cuda_runtime.h>
#include <cuda_bf16.h>
#include <cuda_fp16.h>
#include <cstdint>

// ---------------------------------------------------------------------------
// LSTM T=512, B=64, IN=512, H=1024.
// Phase 1 (HMMA bf16 3-term split): gx[t][cta][b][vn] = x_t @ Wx + bias.
// Phase 2 (persistent, 128 CTAs x 512 thr): EXACT R9 structure, but the
//   recurrent GEMM runs fp16 2-term: h stored as ONE fp16 array (2^-11),
//   Wh as fp16 hi/lo scaled by 2^10 (descale in epilogue).
//   -> 2048 MMA (was 3072), 512 staging cp16 (was 1024), A-L2 traffic halved.
// ---------------------------------------------------------------------------

static constexpr int kT  = 512;
static constexpr int kB  = 64;
static constexpr int kIN = 512;
static constexpr int kH  = 1024;
static constexpr int kBH = kB * kH;
static constexpr int NBLK = 128;
static constexpr float W_SCALE   = 1024.0f;
static constexpr float W_DESCALE = 1.0f / 1024.0f;

__device__ float g_gx2[(size_t)kT * NBLK * kB * 32];      // [t][cta][b][vn]
__device__ __half g_whi2[(size_t)NBLK * 32768];           // per-CTA Wh hi (x2^10)
__device__ __half g_wlo2[(size_t)NBLK * 32768];           // per-CTA Wh lo (x2^10)
__device__ __half g_h16[kB * kH];                         // h fp16 [b][k]
__device__ __nv_bfloat16 g_xhi[(size_t)kT * kB * kIN];    // x hi [m][k]
__device__ __nv_bfloat16 g_xlo[(size_t)kT * kB * kIN];    // x lo
__device__ __nv_bfloat16 g_wxhi[(size_t)4096 * kIN];      // Wx hi [n=4096][k=512]
__device__ __nv_bfloat16 g_wxlo[(size_t)4096 * kIN];      // Wx lo
__device__ unsigned g_bar;

__device__ __forceinline__ uint32_t smem_u32(const void* p) {
    uint32_t a;
    asm("{ .reg .u64 t; cvta.to.shared.u64 t, %1; cvt.u32.u64 %0, t; }"
        : "=r"(a) : "l"(p));
    return a;
}
__device__ __forceinline__ void ldsm_x4(uint32_t* r, uint32_t addr) {
    asm volatile("ldmatrix.sync.aligned.m8n8.x4.shared.b16 {%0,%1,%2,%3}, [%4];"
                 : "=r"(r[0]), "=r"(r[1]), "=r"(r[2]), "=r"(r[3]) : "r"(addr));
}
__device__ __forceinline__ void mma_bf16(float* c, const uint32_t* a,
                                         uint32_t b0, uint32_t b1) {
    asm volatile(
        "mma.sync.aligned.m16n8k16.row.col.f32.bf16.bf16.f32 "
        "{%0,%1,%2,%3}, {%4,%5,%6,%7}, {%8,%9}, {%0,%1,%2,%3};"
        : "+f"(c[0]), "+f"(c[1]), "+f"(c[2]), "+f"(c[3])
        : "r"(a[0]), "r"(a[1]), "r"(a[2]), "r"(a[3]), "r"(b0), "r"(b1));
}
__device__ __forceinline__ void mma_f16(float* c, const uint32_t* a,
                                        uint32_t b0, uint32_t b1) {
    asm volatile(
        "mma.sync.aligned.m16n8k16.row.col.f32.f16.f16.f32 "
        "{%0,%1,%2,%3}, {%4,%5,%6,%7}, {%8,%9}, {%0,%1,%2,%3};"
        : "+f"(c[0]), "+f"(c[1]), "+f"(c[2]), "+f"(c[3])
        : "r"(a[0]), "r"(a[1]), "r"(a[2]), "r"(a[3]), "r"(b0), "r"(b1));
}
__device__ __forceinline__ void cp16(uint32_t dst, const void* src) {
    asm volatile("cp.async.cg.shared.global [%0], [%1], 16;"
                 :: "r"(dst), "l"(src) : "memory");
}
__device__ __forceinline__ void cp_commit() {
    asm volatile("cp.async.commit_group;" ::: "memory");
}
__device__ __forceinline__ void cp_wait1() {
    asm volatile("cp.async.wait_group 1;" ::: "memory");
}
__device__ __forceinline__ void cp_wait0() {
    asm volatile("cp.async.wait_group 0;" ::: "memory");
}
__device__ __forceinline__ float sigmoidf_(float x) {
    return 1.0f / (1.0f + __expf(-x));
}
__device__ __forceinline__ void bar_arrive_release(unsigned* p) {
    asm volatile("red.release.gpu.global.add.u32 [%0], 1;" :: "l"(p) : "memory");
}
__device__ __forceinline__ unsigned ld_acquire(unsigned* p) {
    unsigned v;
    asm volatile("ld.acquire.gpu.global.u32 %0, [%1];" : "=r"(v) : "l"(p) : "memory");
    return v;
}

__global__ void reset_kernel() { g_bar = 0u; }

// ---------------------------------------------------------------------------
// Prep kernels
// ---------------------------------------------------------------------------
__device__ __forceinline__ void split_bf16(float v, __nv_bfloat16& hi, __nv_bfloat16& lo) {
    hi = __float2bfloat16_rn(v);
    lo = __float2bfloat16_rn(v - __bfloat162float(hi));
}

__global__ void __launch_bounds__(256) prep_x(const float* __restrict__ x) {
    size_t i = (size_t)blockIdx.x * 256 + threadIdx.x;
    __nv_bfloat16 hi, lo;
    split_bf16(x[i], hi, lo);
    g_xhi[i] = hi; g_xlo[i] = lo;
}

__global__ void __launch_bounds__(256) prep_wx(
    const float* __restrict__ Wf, const float* __restrict__ Wi,
    const float* __restrict__ Wc, const float* __restrict__ Wo)
{
    size_t i = (size_t)blockIdx.x * 256 + threadIdx.x;   // 4096*512 total
    int n = (int)(i >> 9), k = (int)(i & 511);
    int gate = n >> 10, h = n & 1023;
    const float* W = (gate == 0) ? Wf : (gate == 1) ? Wi : (gate == 2) ? Wc : Wo;
    __nv_bfloat16 hi, lo;
    split_bf16(W[(size_t)(kH + k) * kH + h], hi, lo);
    g_wxhi[i] = hi; g_wxlo[i] = lo;
}

// Wh -> fp16 hi/lo, scaled by 2^10. Blocked per-CTA [n=32][k=1024] rows.
__global__ void __launch_bounds__(256) prep_weights(
    const float* __restrict__ Wf, const float* __restrict__ Wi,
    const float* __restrict__ Wc, const float* __restrict__ Wo)
{
    const int cta = blockIdx.x;
    const int n0h = cta * 8;
    for (int g = 0; g < 4; g++) {
        const float* W = (g == 0) ? Wf : (g == 1) ? Wi : (g == 2) ? Wc : Wo;
        for (int idx = threadIdx.x; idx < 8 * kH; idx += 256) {
            int col = idx & 7, r = idx >> 3;
            float v = W[(size_t)r * kH + n0h + col] * W_SCALE;
            __half hi = __float2half_rn(v);
            __half lo = __float2half_rn(v - __half2float(hi));
            size_t o = (size_t)cta * 32768 + (size_t)(g * 8 + col) * kH + r;
            g_whi2[o] = hi;
            g_wlo2[o] = lo;
        }
    }
}

// ---------------------------------------------------------------------------
// Phase 1 HMMA: gx = X @ Wx + b.  (proven R9, unchanged)
// ---------------------------------------------------------------------------
static constexpr uint32_t P1_AB = 18432;   // 128 rows * 144 B
static constexpr uint32_t P1_OFFB = 4 * P1_AB;          // 73728
static constexpr uint32_t P1_SM = 8 * P1_AB;            // 147456

__global__ void __launch_bounds__(512, 1) phase1_hmma(
    const float* __restrict__ bf, const float* __restrict__ bi,
    const float* __restrict__ bc, const float* __restrict__ bo)
{
    extern __shared__ __align__(128) char smem[];
    const uint32_t sb = smem_u32(smem);
    const int tid  = threadIdx.x;
    const int wid  = tid >> 5;
    const int lane = tid & 31;
    const int mi2  = wid & 3;
    const int nw   = wid >> 2;
    const int n0   = blockIdx.x * 128;
    const int m0   = blockIdx.y * 128;
    const int gate = n0 >> 10;
    const float* biasg = (gate == 0) ? bf : (gate == 1) ? bi : (gate == 2) ? bc : bo;

    const int s_row0 = tid >> 3, s_c16 = tid & 7;
    const int s_row1 = (tid + 512) >> 3;
    const uint32_t so0 = (uint32_t)(s_row0 * 144 + s_c16 * 16);
    const uint32_t so1 = (uint32_t)(s_row1 * 144 + s_c16 * 16);

    auto stage = [&](int c) {
        const int buf = c & 1;
        const uint32_t ahi = sb + buf * 2 * P1_AB;
        const uint32_t alo = ahi + P1_AB;
        const uint32_t bhi = sb + P1_OFFB + buf * 2 * P1_AB;
        const uint32_t blo = bhi + P1_AB;
        const size_t ga0 = (size_t)(m0 + s_row0) * kIN + c * 64 + s_c16 * 8;
        const size_t ga1 = (size_t)(m0 + s_row1) * kIN + c * 64 + s_c16 * 8;
        const size_t gb0 = (size_t)(n0 + s_row0) * kIN + c * 64 + s_c16 * 8;
        const size_t gb1 = (size_t)(n0 + s_row1) * kIN + c * 64 + s_c16 * 8;
        cp16(ahi + so0, &g_xhi[ga0]);  cp16(ahi + so1, &g_xhi[ga1]);
        cp16(alo + so0, &g_xlo[ga0]);  cp16(alo + so1, &g_xlo[ga1]);
        cp16(bhi + so0, &g_wxhi[gb0]); cp16(bhi + so1, &g_wxhi[gb1]);
        cp16(blo + so0, &g_wxlo[gb0]); cp16(blo + so1, &g_wxlo[gb1]);
    };

    uint32_t aoff[2];
#pragma unroll
    for (int i = 0; i < 2; i++)
        aoff[i] = (uint32_t)((32 * mi2 + 16 * i + (lane & 15)) * 144 + (lane >> 4) * 16);
    uint32_t boff[2];
#pragma unroll
    for (int j = 0; j < 2; j++)
        boff[j] = (uint32_t)((32 * nw + 16 * j + (lane & 7) + ((lane >> 4) << 3)) * 144
                             + ((lane >> 3) & 1) * 16);

    float C[2][2][2][4];
#pragma unroll
    for (int i = 0; i < 2; i++)
#pragma unroll
        for (int j = 0; j < 2; j++)
#pragma unroll
            for (int h2 = 0; h2 < 2; h2++)
#pragma unroll
                for (int q = 0; q < 4; q++) C[i][j][h2][q] = 0.0f;

    stage(0); cp_commit();

    for (int c = 0; c < 8; ++c) {
        if (c + 1 < 8) stage(c + 1);
        cp_commit();
        if (c + 1 < 8) cp_wait1(); else cp_wait0();
        __syncthreads();
        const int buf = c & 1;
        const uint32_t ahi = sb + buf * 2 * P1_AB;
        const uint32_t alo = ahi + P1_AB;
        const uint32_t bhi = sb + P1_OFFB + buf * 2 * P1_AB;
        const uint32_t blo = bhi + P1_AB;
#pragma unroll
        for (int u = 0; u < 4; ++u) {
            uint32_t ah[2][4], al[2][4], bh[2][4], bl[2][4];
#pragma unroll
            for (int i = 0; i < 2; i++) {
                ldsm_x4(ah[i], ahi + aoff[i] + u * 32);
                ldsm_x4(al[i], alo + aoff[i] + u * 32);
            }
#pragma unroll
            for (int j = 0; j < 2; j++) {
                ldsm_x4(bh[j], bhi + boff[j] + u * 32);
                ldsm_x4(bl[j], blo + boff[j] + u * 32);
            }
#pragma unroll
            for (int i = 0; i < 2; i++)
#pragma unroll
                for (int j = 0; j < 2; j++) {
                    mma_bf16(C[i][j][0], ah[i], bh[j][0], bh[j][1]);
                    mma_bf16(C[i][j][1], ah[i], bh[j][2], bh[j][3]);
                    mma_bf16(C[i][j][0], ah[i], bl[j][0], bl[j][1]);
                    mma_bf16(C[i][j][1], ah[i], bl[j][2], bl[j][3]);
                    mma_bf16(C[i][j][0], al[i], bh[j][0], bh[j][1]);
                    mma_bf16(C[i][j][1], al[i], bh[j][2], bh[j][3]);
                }
        }
        __syncthreads();
    }

    // epilogue: bias + scattered gx2 stores (float2, even offsets)
#pragma unroll
    for (int j = 0; j < 2; j++)
#pragma unroll
        for (int h2 = 0; h2 < 2; h2++) {
            const int col = 32 * nw + 16 * j + 8 * h2 + (lane & 3) * 2;
            const int n = n0 + col;
            const int hh = n & 1023;
            const int cta = hh >> 3, jj = hh & 7;
            const float b0 = biasg[hh], b1 = biasg[hh + 1];
#pragma unroll
            for (int i = 0; i < 2; i++)
#pragma unroll
                for (int rr = 0; rr < 2; rr++) {
                    const int r = 32 * mi2 + 16 * i + (lane >> 2) + 8 * rr;
                    const int m = m0 + r;
                    const int t = m >> 6, b = m & 63;
                    float2 v;
                    v.x = C[i][j][h2][2 * rr]     + b0;
                    v.y = C[i][j][h2][2 * rr + 1] + b1;
                    *reinterpret_cast<float2*>(
                        &g_gx2[(((size_t)t * NBLK + cta) * kB + b) * 32 + gate * 8 + jj]) = v;
                }
        }
}

// ---------------------------------------------------------------------------
// Persistent HMMA phase 2, v7 = R9 structure, fp16 2-term math.
// 128 CTAs x 512 threads. Warp w: mi = w&3 (m16), ks = w>>2 (k16/chunk).
// A single fp16 array, ring-3 buffers (one array per chunk).
// ---------------------------------------------------------------------------
static constexpr uint32_t SB_STRIDE = 2064;
static constexpr uint32_t OFF_BHI = 0;
static constexpr uint32_t OFF_BLO = 32 * SB_STRIDE;              // 66048
static constexpr uint32_t OFF_A   = 2 * 32 * SB_STRIDE;          // 132096
static constexpr uint32_t ABUF    = 9216;                        // 64 * 144
static constexpr int      PRE_STRIDE = 34;                       // floats (even)
static constexpr int      PRE_FLOATS = 64 * PRE_STRIDE;          // 2176
static constexpr uint32_t OFF_PRE = OFF_A + 3 * ABUF;            // 159744
static constexpr uint32_t SM_TOTAL2 = OFF_PRE + 4 * PRE_FLOATS * 4;  // 194560

__global__ void __launch_bounds__(512, 1) lstm_hmma7(float* __restrict__ out)
{
    extern __shared__ __align__(128) char smem[];
    const uint32_t sb = smem_u32(smem);

    const int tid  = threadIdx.x;
    const int wid  = tid >> 5;
    const int lane = tid & 31;
    const int bx   = blockIdx.x;
    const int n0h  = bx * 8;
    const int mi   = wid & 3;
    const int ks   = wid >> 2;

    // resident weights (fp16 hi/lo)
    {
        const uint4* shi = reinterpret_cast<const uint4*>(&g_whi2[(size_t)bx * 32768]);
        const uint4* slo = reinterpret_cast<const uint4*>(&g_wlo2[(size_t)bx * 32768]);
        for (int i = tid; i < 4096; i += 512) {
            int n = i >> 7, c8 = i & 127;
            uint32_t o = n * SB_STRIDE + c8 * 16;
            *reinterpret_cast<uint4*>(smem + OFF_BHI + o) = shi[i];
            *reinterpret_cast<uint4*>(smem + OFF_BLO + o) = slo[i];
        }
    }
    g_h16[bx * 512 + tid] = __float2half(0.0f);
    __syncthreads();
    if (tid == 0) {
        bar_arrive_release(&g_bar);
        while (ld_acquire(&g_bar) < NBLK) { __nanosleep(16); }
    }
    __syncthreads();

    // fragment bases (R9 mappings)
    const uint32_t a_off = (uint32_t)((16 * mi + (lane & 15)) * 144
                                      + (lane >> 4) * 16 + ks * 32);
    uint32_t bHi[2], bLo[2];
#pragma unroll
    for (int j = 0; j < 2; j++) {
        const uint32_t b_row = 16 * j + (lane & 7) + ((lane >> 4) << 3);
        bHi[j] = sb + OFF_BHI + b_row * SB_STRIDE + ((lane >> 3) & 1) * 16;
        bLo[j] = sb + OFF_BLO + b_row * SB_STRIDE + ((lane >> 3) & 1) * 16;
    }

    // staging: ONE 16B slot per thread (64 rows x 8 uint4 = 512 slots)
    const int s_row0 = tid >> 3, s_c16 = tid & 7;
    const uint32_t so0 = (uint32_t)(s_row0 * 144 + s_c16 * 16);

    // gate-update mapping
    const int ub = tid >> 3, uj = tid & 7;
    float* pre0 = reinterpret_cast<float*>(smem + OFF_PRE);
    float* pre1 = pre0 + PRE_FLOATS;
    float* pre2 = pre1 + PRE_FLOATS;
    float* pre3 = pre2 + PRE_FLOATS;
    float* preK = pre0 + ks * PRE_FLOATS;

    float c_reg = 0.0f;

    float gx4[4];
    {
        const float* gx = &g_gx2[(((size_t)0 * NBLK + bx) * kB + ub) * 32];
#pragma unroll
        for (int g = 0; g < 4; ++g) gx4[g] = gx[8 * g + uj];
    }

    auto stageA = [&](int c) {
        const int buf = c % 3;
        const uint32_t abase = sb + OFF_A + buf * ABUF;
        const size_t g0 = (size_t)s_row0 * kH + c * 64 + s_c16 * 8;
        cp16(abase + so0, &g_h16[g0]);
    };

    for (int t = 0; t < kT; ++t) {
        float C00[4] = {0,0,0,0}, C01[4] = {0,0,0,0};
        float C10[4] = {0,0,0,0}, C11[4] = {0,0,0,0};

        stageA(0); cp_commit();
        stageA(1); cp_commit();

        for (int c = 0; c < 16; ++c) {
            cp_wait1();
            __syncthreads();
            if (c + 2 < 16) stageA(c + 2);
            cp_commit();

            const int buf = c % 3;
            const uint32_t abase = sb + OFF_A + buf * ABUF;
            uint32_t ah[4], bh0[4], bh1[4], bl0[4], bl1[4];
            ldsm_x4(ah, abase + a_off);
            const uint32_t bo = (uint32_t)(c * 128 + ks * 32);
            ldsm_x4(bh0, bHi[0] + bo);
            ldsm_x4(bh1, bHi[1] + bo);
            ldsm_x4(bl0, bLo[0] + bo);
            ldsm_x4(bl1, bLo[1] + bo);
            mma_f16(C00, ah, bh0[0], bh0[1]); mma_f16(C01, ah, bh0[2], bh0[3]);
            mma_f16(C10, ah, bh1[0], bh1[1]); mma_f16(C11, ah, bh1[2], bh1[3]);
            mma_f16(C00, ah, bl0[0], bl0[1]); mma_f16(C01, ah, bl0[2], bl0[3]);
            mma_f16(C10, ah, bl1[0], bl1[1]); mma_f16(C11, ah, bl1[2], bl1[3]);
        }

        // publish partials into pre[ks] (stride 34 -> float2 stores aligned)
        {
            const int r0 = 16 * mi + (lane >> 2);
            const int cb = (lane & 3) * 2;
            float2 v;
            v.x = C00[0]; v.y = C00[1];
            *reinterpret_cast<float2*>(&preK[r0 * PRE_STRIDE + cb]) = v;
            v.x = C00[2]; v.y = C00[3];
            *reinterpret_cast<float2*>(&preK[(r0 + 8) * PRE_STRIDE + cb]) = v;
            v.x = C01[0]; v.y = C01[1];
            *reinterpret_cast<float2*>(&preK[r0 * PRE_STRIDE + cb + 8]) = v;
            v.x = C01[2]; v.y = C01[3];
            *reinterpret_cast<float2*>(&preK[(r0 + 8) * PRE_STRIDE + cb + 8]) = v;
            v.x = C10[0]; v.y = C10[1];
            *reinterpret_cast<float2*>(&preK[r0 * PRE_STRIDE + cb + 16]) = v;
            v.x = C10[2]; v.y = C10[3];
            *reinterpret_cast<float2*>(&preK[(r0 + 8) * PRE_STRIDE + cb + 16]) = v;
            v.x = C11[0]; v.y = C11[1];
            *reinterpret_cast<float2*>(&preK[r0 * PRE_STRIDE + cb + 24]) = v;
            v.x = C11[2]; v.y = C11[3];
            *reinterpret_cast<float2*>(&preK[(r0 + 8) * PRE_STRIDE + cb + 24]) = v;
        }
        __syncthreads();

        // gate math + c/h update (1 item/thread); descale W by 2^-10
        {
            const int b = ub, j = uj;
            const int o0 = b * PRE_STRIDE + j;
            float pf = (pre0[o0]      + pre1[o0]      + pre2[o0]      + pre3[o0])      * W_DESCALE + gx4[0];
            float pi = (pre0[o0 + 8]  + pre1[o0 + 8]  + pre2[o0 + 8]  + pre3[o0 + 8])  * W_DESCALE + gx4[1];
            float pg = (pre0[o0 + 16] + pre1[o0 + 16] + pre2[o0 + 16] + pre3[o0 + 16]) * W_DESCALE + gx4[2];
            float po = (pre0[o0 + 24] + pre1[o0 + 24] + pre2[o0 + 24] + pre3[o0 + 24]) * W_DESCALE + gx4[3];
            float f  = sigmoidf_(pf);
            float ii = sigmoidf_(pi);
            float gg = tanhf(pg);
            float oo = sigmoidf_(po);
            float cn = f * c_reg + ii * gg;
            c_reg = cn;
            float h = oo * tanhf(cn);
            out[(size_t)t * kBH + (size_t)b * kH + n0h + j] = h;
            g_h16[b * kH + n0h + j] = __float2half_rn(h);
            if (t == kT - 1) {
                out[(size_t)kT * kBH + (size_t)b * kH + n0h + j] = h;
                out[(size_t)kT * kBH + kBH + (size_t)b * kH + n0h + j] = cn;
            }
        }

        // split global barrier (release arrive, gx prefetch, acquire wait)
        if (t < kT - 1) {
            __syncthreads();
            if (tid == 0) bar_arrive_release(&g_bar);
            {
                const float* gx = &g_gx2[(((size_t)(t + 1) * NBLK + bx) * kB + ub) * 32];
#pragma unroll
                for (int g = 0; g < 4; ++g) gx4[g] = gx[8 * g + uj];
            }
            if (tid == 0) {
                const unsigned tgt = (unsigned)(t + 2) * NBLK;
                while (ld_acquire(&g_bar) < tgt) { __nanosleep(16); }
            }
            __syncthreads();
        }
    }
}

// ---------------------------------------------------------------------------
extern "C" void kernel_launch(void* const* d_in, const int* in_sizes, int n_in,
                              void* d_out, int out_size)
{
    const float* x  = (const float*)d_in[0];
    const float* Wf = (const float*)d_in[1];
    const float* bf = (const float*)d_in[2];
    const float* Wi = (const float*)d_in[3];
    const float* bi = (const float*)d_in[4];
    const float* Wc = (const float*)d_in[5];
    const float* bc = (const float*)d_in[6];
    const float* Wo = (const float*)d_in[7];
    const float* bo = (const float*)d_in[8];
    float* out = (float*)d_out;

    cudaFuncSetAttribute(phase1_hmma,
                         cudaFuncAttributeMaxDynamicSharedMemorySize, P1_SM);
    cudaFuncSetAttribute(lstm_hmma7,
                         cudaFuncAttributeMaxDynamicSharedMemorySize, SM_TOTAL2);

    reset_kernel<<<1, 1>>>();
    prep_x<<<(kT * kB * kIN) / 256, 256>>>(x);
    prep_wx<<<(4096 * kIN) / 256, 256>>>(Wf, Wi, Wc, Wo);
    prep_weights<<<NBLK, 256>>>(Wf, Wi, Wc, Wo);

    dim3 g1(4096 / 128, (kT * kB) / 128);   // 32 x 256
    phase1_hmma<<<g1, 512, P1_SM>>>(bf, bi, bc, bo);

    lstm_hmma7<<<NBLK, 512, SM_TOTAL2>>>(out);
}

// round 14
// speedup vs baseline: 1.8127x; 1.0999x over previous
#include <cuda_runtime.h>
#include <cuda_bf16.h>
#include <cuda_fp16.h>
#include <cstdint>

// ---------------------------------------------------------------------------
// LSTM T=512, B=64, IN=512, H=1024.
// Phase 1 (HMMA fp16 2-term): gx = x16 @ (Wx*2^10 hi/lo) / 2^10 + bias.
// Phase 2 (persistent, 128 CTAs x 512 thr, R9/R13 structure): recurrent GEMM
//   h16 @ (Wh*2^10 fp16) single-term, fp32 accum, descale in epilogue.
//   16 warps = 4 m-tiles x 4 k-slices; cp.async ring-3 A staging; 4 pre
//   partial buffers; c in registers; split global barrier.
// ---------------------------------------------------------------------------

static constexpr int kT  = 512;
static constexpr int kB  = 64;
static constexpr int kIN = 512;
static constexpr int kH  = 1024;
static constexpr int kBH = kB * kH;
static constexpr int NBLK = 128;
static constexpr float W_SCALE   = 1024.0f;
static constexpr float W_DESCALE = 1.0f / 1024.0f;

__device__ float g_gx2[(size_t)kT * NBLK * kB * 32];      // [t][cta][b][vn]
__device__ __half g_w16[(size_t)NBLK * 32768];            // per-CTA Wh (x2^10) fp16
__device__ __half g_h16[kB * kH];                         // h fp16 [b][k]
__device__ __half g_x16[(size_t)kT * kB * kIN];           // x fp16 [m][k]
__device__ __half g_wxhi[(size_t)4096 * kIN];             // Wx hi (x2^10) [n][k]
__device__ __half g_wxlo[(size_t)4096 * kIN];             // Wx lo (x2^10)
__device__ unsigned g_bar;

__device__ __forceinline__ uint32_t smem_u32(const void* p) {
    uint32_t a;
    asm("{ .reg .u64 t; cvta.to.shared.u64 t, %1; cvt.u32.u64 %0, t; }"
        : "=r"(a) : "l"(p));
    return a;
}
__device__ __forceinline__ void ldsm_x4(uint32_t* r, uint32_t addr) {
    asm volatile("ldmatrix.sync.aligned.m8n8.x4.shared.b16 {%0,%1,%2,%3}, [%4];"
                 : "=r"(r[0]), "=r"(r[1]), "=r"(r[2]), "=r"(r[3]) : "r"(addr));
}
__device__ __forceinline__ void mma_f16(float* c, const uint32_t* a,
                                        uint32_t b0, uint32_t b1) {
    asm volatile(
        "mma.sync.aligned.m16n8k16.row.col.f32.f16.f16.f32 "
        "{%0,%1,%2,%3}, {%4,%5,%6,%7}, {%8,%9}, {%0,%1,%2,%3};"
        : "+f"(c[0]), "+f"(c[1]), "+f"(c[2]), "+f"(c[3])
        : "r"(a[0]), "r"(a[1]), "r"(a[2]), "r"(a[3]), "r"(b0), "r"(b1));
}
__device__ __forceinline__ void cp16(uint32_t dst, const void* src) {
    asm volatile("cp.async.cg.shared.global [%0], [%1], 16;"
                 :: "r"(dst), "l"(src) : "memory");
}
__device__ __forceinline__ void cp_commit() {
    asm volatile("cp.async.commit_group;" ::: "memory");
}
__device__ __forceinline__ void cp_wait1() {
    asm volatile("cp.async.wait_group 1;" ::: "memory");
}
__device__ __forceinline__ void cp_wait0() {
    asm volatile("cp.async.wait_group 0;" ::: "memory");
}
__device__ __forceinline__ float sigmoidf_(float x) {
    return 1.0f / (1.0f + __expf(-x));
}
__device__ __forceinline__ void bar_arrive_release(unsigned* p) {
    asm volatile("red.release.gpu.global.add.u32 [%0], 1;" :: "l"(p) : "memory");
}
__device__ __forceinline__ unsigned ld_acquire(unsigned* p) {
    unsigned v;
    asm volatile("ld.acquire.gpu.global.u32 %0, [%1];" : "=r"(v) : "l"(p) : "memory");
    return v;
}

__global__ void reset_kernel() { g_bar = 0u; }

// ---------------------------------------------------------------------------
// Prep kernels
// ---------------------------------------------------------------------------
__global__ void __launch_bounds__(256) prep_x(const float* __restrict__ x) {
    size_t i = (size_t)blockIdx.x * 256 + threadIdx.x;
    g_x16[i] = __float2half_rn(x[i]);
}

__global__ void __launch_bounds__(256) prep_wx(
    const float* __restrict__ Wf, const float* __restrict__ Wi,
    const float* __restrict__ Wc, const float* __restrict__ Wo)
{
    size_t i = (size_t)blockIdx.x * 256 + threadIdx.x;   // 4096*512 total
    int n = (int)(i >> 9), k = (int)(i & 511);
    int gate = n >> 10, h = n & 1023;
    const float* W = (gate == 0) ? Wf : (gate == 1) ? Wi : (gate == 2) ? Wc : Wo;
    float v = W[(size_t)(kH + k) * kH + h] * W_SCALE;
    __half hi = __float2half_rn(v);
    __half lo = __float2half_rn(v - __half2float(hi));
    g_wxhi[i] = hi; g_wxlo[i] = lo;
}

// Wh -> single fp16, scaled by 2^10. Blocked per-CTA [n=32][k=1024] rows.
__global__ void __launch_bounds__(256) prep_weights(
    const float* __restrict__ Wf, const float* __restrict__ Wi,
    const float* __restrict__ Wc, const float* __restrict__ Wo)
{
    const int cta = blockIdx.x;
    const int n0h = cta * 8;
    for (int g = 0; g < 4; g++) {
        const float* W = (g == 0) ? Wf : (g == 1) ? Wi : (g == 2) ? Wc : Wo;
        for (int idx = threadIdx.x; idx < 8 * kH; idx += 256) {
            int col = idx & 7, r = idx >> 3;
            float v = W[(size_t)r * kH + n0h + col] * W_SCALE;
            g_w16[(size_t)cta * 32768 + (size_t)(g * 8 + col) * kH + r] =
                __float2half_rn(v);
        }
    }
}

// ---------------------------------------------------------------------------
// Phase 1 HMMA (fp16 2-term): gx = X @ Wx + b.  M=32768, N=4096, K=512.
// Tile BM=128 x BN=128 x BK=64. 512 thr, 16 warps = 4 m32 x 4 n32.
// ---------------------------------------------------------------------------
static constexpr uint32_t P1_AB = 18432;   // 128 rows * 144 B
static constexpr uint32_t P1_OFFB = 2 * P1_AB;          // 36864
static constexpr uint32_t P1_SM = 6 * P1_AB;            // 110592

__global__ void __launch_bounds__(512, 1) phase1_hmma(
    const float* __restrict__ bf, const float* __restrict__ bi,
    const float* __restrict__ bc, const float* __restrict__ bo)
{
    extern __shared__ __align__(128) char smem[];
    const uint32_t sb = smem_u32(smem);
    const int tid  = threadIdx.x;
    const int wid  = tid >> 5;
    const int lane = tid & 31;
    const int mi2  = wid & 3;
    const int nw   = wid >> 2;
    const int n0   = blockIdx.x * 128;
    const int m0   = blockIdx.y * 128;
    const int gate = n0 >> 10;
    const float* biasg = (gate == 0) ? bf : (gate == 1) ? bi : (gate == 2) ? bc : bo;

    const int s_row0 = tid >> 3, s_c16 = tid & 7;
    const int s_row1 = (tid + 512) >> 3;
    const uint32_t so0 = (uint32_t)(s_row0 * 144 + s_c16 * 16);
    const uint32_t so1 = (uint32_t)(s_row1 * 144 + s_c16 * 16);

    auto stage = [&](int c) {
        const int buf = c & 1;
        const uint32_t a   = sb + buf * P1_AB;
        const uint32_t bhi = sb + P1_OFFB + buf * 2 * P1_AB;
        const uint32_t blo = bhi + P1_AB;
        const size_t ga0 = (size_t)(m0 + s_row0) * kIN + c * 64 + s_c16 * 8;
        const size_t ga1 = (size_t)(m0 + s_row1) * kIN + c * 64 + s_c16 * 8;
        const size_t gb0 = (size_t)(n0 + s_row0) * kIN + c * 64 + s_c16 * 8;
        const size_t gb1 = (size_t)(n0 + s_row1) * kIN + c * 64 + s_c16 * 8;
        cp16(a + so0, &g_x16[ga0]);    cp16(a + so1, &g_x16[ga1]);
        cp16(bhi + so0, &g_wxhi[gb0]); cp16(bhi + so1, &g_wxhi[gb1]);
        cp16(blo + so0, &g_wxlo[gb0]); cp16(blo + so1, &g_wxlo[gb1]);
    };

    uint32_t aoff[2];
#pragma unroll
    for (int i = 0; i < 2; i++)
        aoff[i] = (uint32_t)((32 * mi2 + 16 * i + (lane & 15)) * 144 + (lane >> 4) * 16);
    uint32_t boff[2];
#pragma unroll
    for (int j = 0; j < 2; j++)
        boff[j] = (uint32_t)((32 * nw + 16 * j + (lane & 7) + ((lane >> 4) << 3)) * 144
                             + ((lane >> 3) & 1) * 16);

    float C[2][2][2][4];
#pragma unroll
    for (int i = 0; i < 2; i++)
#pragma unroll
        for (int j = 0; j < 2; j++)
#pragma unroll
            for (int h2 = 0; h2 < 2; h2++)
#pragma unroll
                for (int q = 0; q < 4; q++) C[i][j][h2][q] = 0.0f;

    stage(0); cp_commit();

    for (int c = 0; c < 8; ++c) {
        if (c + 1 < 8) stage(c + 1);
        cp_commit();
        if (c + 1 < 8) cp_wait1(); else cp_wait0();
        __syncthreads();
        const int buf = c & 1;
        const uint32_t a   = sb + buf * P1_AB;
        const uint32_t bhi = sb + P1_OFFB + buf * 2 * P1_AB;
        const uint32_t blo = bhi + P1_AB;
#pragma unroll
        for (int u = 0; u < 4; ++u) {
            uint32_t ah[2][4], bh[2][4], bl[2][4];
#pragma unroll
            for (int i = 0; i < 2; i++)
                ldsm_x4(ah[i], a + aoff[i] + u * 32);
#pragma unroll
            for (int j = 0; j < 2; j++) {
                ldsm_x4(bh[j], bhi + boff[j] + u * 32);
                ldsm_x4(bl[j], blo + boff[j] + u * 32);
            }
#pragma unroll
            for (int i = 0; i < 2; i++)
#pragma unroll
                for (int j = 0; j < 2; j++) {
                    mma_f16(C[i][j][0], ah[i], bh[j][0], bh[j][1]);
                    mma_f16(C[i][j][1], ah[i], bh[j][2], bh[j][3]);
                    mma_f16(C[i][j][0], ah[i], bl[j][0], bl[j][1]);
                    mma_f16(C[i][j][1], ah[i], bl[j][2], bl[j][3]);
                }
        }
        __syncthreads();
    }

    // epilogue: descale + bias + scattered gx2 stores (float2, even offsets)
#pragma unroll
    for (int j = 0; j < 2; j++)
#pragma unroll
        for (int h2 = 0; h2 < 2; h2++) {
            const int col = 32 * nw + 16 * j + 8 * h2 + (lane & 3) * 2;
            const int n = n0 + col;
            const int hh = n & 1023;
            const int cta = hh >> 3, jj = hh & 7;
            const float b0 = biasg[hh], b1 = biasg[hh + 1];
#pragma unroll
            for (int i = 0; i < 2; i++)
#pragma unroll
                for (int rr = 0; rr < 2; rr++) {
                    const int r = 32 * mi2 + 16 * i + (lane >> 2) + 8 * rr;
                    const int m = m0 + r;
                    const int t = m >> 6, b = m & 63;
                    float2 v;
                    v.x = C[i][j][h2][2 * rr]     * W_DESCALE + b0;
                    v.y = C[i][j][h2][2 * rr + 1] * W_DESCALE + b1;
                    *reinterpret_cast<float2*>(
                        &g_gx2[(((size_t)t * NBLK + cta) * kB + b) * 32 + gate * 8 + jj]) = v;
                }
        }
}

// ---------------------------------------------------------------------------
// Persistent HMMA phase 2, v8 = R13 structure, single-term fp16 W.
// 128 CTAs x 512 threads. Warp w: mi = w&3 (m16), ks = w>>2 (k16/chunk).
// ---------------------------------------------------------------------------
static constexpr uint32_t SB_STRIDE = 2064;
static constexpr uint32_t OFF_BW  = 0;                           // 32 rows W
static constexpr uint32_t OFF_A   = 32 * SB_STRIDE;              // 66048
static constexpr uint32_t ABUF    = 9216;                        // 64 * 144
static constexpr int      PRE_STRIDE = 34;                       // floats (even)
static constexpr int      PRE_FLOATS = 64 * PRE_STRIDE;          // 2176
static constexpr uint32_t OFF_PRE = OFF_A + 3 * ABUF;            // 93696
static constexpr uint32_t SM_TOTAL2 = OFF_PRE + 4 * PRE_FLOATS * 4;  // 128512

__global__ void __launch_bounds__(512, 1) lstm_hmma8(float* __restrict__ out)
{
    extern __shared__ __align__(128) char smem[];
    const uint32_t sb = smem_u32(smem);

    const int tid  = threadIdx.x;
    const int wid  = tid >> 5;
    const int lane = tid & 31;
    const int bx   = blockIdx.x;
    const int n0h  = bx * 8;
    const int mi   = wid & 3;
    const int ks   = wid >> 2;

    // resident weights (single fp16 array)
    {
        const uint4* sw = reinterpret_cast<const uint4*>(&g_w16[(size_t)bx * 32768]);
        for (int i = tid; i < 4096; i += 512) {
            int n = i >> 7, c8 = i & 127;
            *reinterpret_cast<uint4*>(smem + OFF_BW + n * SB_STRIDE + c8 * 16) = sw[i];
        }
    }
    g_h16[bx * 512 + tid] = __float2half(0.0f);
    __syncthreads();
    if (tid == 0) {
        bar_arrive_release(&g_bar);
        while (ld_acquire(&g_bar) < NBLK) { __nanosleep(16); }
    }
    __syncthreads();

    // fragment bases (R9 mappings)
    const uint32_t a_off = (uint32_t)((16 * mi + (lane & 15)) * 144
                                      + (lane >> 4) * 16 + ks * 32);
    uint32_t bW[2];
#pragma unroll
    for (int j = 0; j < 2; j++) {
        const uint32_t b_row = 16 * j + (lane & 7) + ((lane >> 4) << 3);
        bW[j] = sb + OFF_BW + b_row * SB_STRIDE + ((lane >> 3) & 1) * 16;
    }

    // staging: ONE 16B slot per thread (64 rows x 8 uint4 = 512 slots)
    const int s_row0 = tid >> 3, s_c16 = tid & 7;
    const uint32_t so0 = (uint32_t)(s_row0 * 144 + s_c16 * 16);

    // gate-update mapping
    const int ub = tid >> 3, uj = tid & 7;
    float* pre0 = reinterpret_cast<float*>(smem + OFF_PRE);
    float* pre1 = pre0 + PRE_FLOATS;
    float* pre2 = pre1 + PRE_FLOATS;
    float* pre3 = pre2 + PRE_FLOATS;
    float* preK = pre0 + ks * PRE_FLOATS;

    float c_reg = 0.0f;

    float gx4[4];
    {
        const float* gx = &g_gx2[(((size_t)0 * NBLK + bx) * kB + ub) * 32];
#pragma unroll
        for (int g = 0; g < 4; ++g) gx4[g] = gx[8 * g + uj];
    }

    auto stageA = [&](int c) {
        const int buf = c % 3;
        const uint32_t abase = sb + OFF_A + buf * ABUF;
        const size_t g0 = (size_t)s_row0 * kH + c * 64 + s_c16 * 8;
        cp16(abase + so0, &g_h16[g0]);
    };

    for (int t = 0; t < kT; ++t) {
        float C00[4] = {0,0,0,0}, C01[4] = {0,0,0,0};
        float C10[4] = {0,0,0,0}, C11[4] = {0,0,0,0};

        stageA(0); cp_commit();
        stageA(1); cp_commit();

        for (int c = 0; c < 16; ++c) {
            cp_wait1();
            __syncthreads();
            if (c + 2 < 16) stageA(c + 2);
            cp_commit();

            const int buf = c % 3;
            const uint32_t abase = sb + OFF_A + buf * ABUF;
            uint32_t ah[4], bw0[4], bw1[4];
            ldsm_x4(ah, abase + a_off);
            const uint32_t bo = (uint32_t)(c * 128 + ks * 32);
            ldsm_x4(bw0, bW[0] + bo);
            ldsm_x4(bw1, bW[1] + bo);
            mma_f16(C00, ah, bw0[0], bw0[1]); mma_f16(C01, ah, bw0[2], bw0[3]);
            mma_f16(C10, ah, bw1[0], bw1[1]); mma_f16(C11, ah, bw1[2], bw1[3]);
        }

        // publish partials into pre[ks] (stride 34 -> float2 stores aligned)
        {
            const int r0 = 16 * mi + (lane >> 2);
            const int cb = (lane & 3) * 2;
            float2 v;
            v.x = C00[0]; v.y = C00[1];
            *reinterpret_cast<float2*>(&preK[r0 * PRE_STRIDE + cb]) = v;
            v.x = C00[2]; v.y = C00[3];
            *reinterpret_cast<float2*>(&preK[(r0 + 8) * PRE_STRIDE + cb]) = v;
            v.x = C01[0]; v.y = C01[1];
            *reinterpret_cast<float2*>(&preK[r0 * PRE_STRIDE + cb + 8]) = v;
            v.x = C01[2]; v.y = C01[3];
            *reinterpret_cast<float2*>(&preK[(r0 + 8) * PRE_STRIDE + cb + 8]) = v;
            v.x = C10[0]; v.y = C10[1];
            *reinterpret_cast<float2*>(&preK[r0 * PRE_STRIDE + cb + 16]) = v;
            v.x = C10[2]; v.y = C10[3];
            *reinterpret_cast<float2*>(&preK[(r0 + 8) * PRE_STRIDE + cb + 16]) = v;
            v.x = C11[0]; v.y = C11[1];
            *reinterpret_cast<float2*>(&preK[r0 * PRE_STRIDE + cb + 24]) = v;
            v.x = C11[2]; v.y = C11[3];
            *reinterpret_cast<float2*>(&preK[(r0 + 8) * PRE_STRIDE + cb + 24]) = v;
        }
        __syncthreads();

        // gate math + c/h update (1 item/thread); descale W by 2^-10
        {
            const int b = ub, j = uj;
            const int o0 = b * PRE_STRIDE + j;
            float pf = (pre0[o0]      + pre1[o0]      + pre2[o0]      + pre3[o0])      * W_DESCALE + gx4[0];
            float pi = (pre0[o0 + 8]  + pre1[o0 + 8]  + pre2[o0 + 8]  + pre3[o0 + 8])  * W_DESCALE + gx4[1];
            float pg = (pre0[o0 + 16] + pre1[o0 + 16] + pre2[o0 + 16] + pre3[o0 + 16]) * W_DESCALE + gx4[2];
            float po = (pre0[o0 + 24] + pre1[o0 + 24] + pre2[o0 + 24] + pre3[o0 + 24]) * W_DESCALE + gx4[3];
            float f  = sigmoidf_(pf);
            float ii = sigmoidf_(pi);
            float gg = tanhf(pg);
            float oo = sigmoidf_(po);
            float cn = f * c_reg + ii * gg;
            c_reg = cn;
            float h = oo * tanhf(cn);
            out[(size_t)t * kBH + (size_t)b * kH + n0h + j] = h;
            g_h16[b * kH + n0h + j] = __float2half_rn(h);
            if (t == kT - 1) {
                out[(size_t)kT * kBH + (size_t)b * kH + n0h + j] = h;
                out[(size_t)kT * kBH + kBH + (size_t)b * kH + n0h + j] = cn;
            }
        }

        // split global barrier (release arrive, gx prefetch, acquire wait)
        if (t < kT - 1) {
            __syncthreads();
            if (tid == 0) bar_arrive_release(&g_bar);
            {
                const float* gx = &g_gx2[(((size_t)(t + 1) * NBLK + bx) * kB + ub) * 32];
#pragma unroll
                for (int g = 0; g < 4; ++g) gx4[g] = gx[8 * g + uj];
            }
            if (tid == 0) {
                const unsigned tgt = (unsigned)(t + 2) * NBLK;
                while (ld_acquire(&g_bar) < tgt) { __nanosleep(16); }
            }
            __syncthreads();
        }
    }
}

// ---------------------------------------------------------------------------
extern "C" void kernel_launch(void* const* d_in, const int* in_sizes, int n_in,
                              void* d_out, int out_size)
{
    const float* x  = (const float*)d_in[0];
    const float* Wf = (const float*)d_in[1];
    const float* bf = (const float*)d_in[2];
    const float* Wi = (const float*)d_in[3];
    const float* bi = (const float*)d_in[4];
    const float* Wc = (const float*)d_in[5];
    const float* bc = (const float*)d_in[6];
    const float* Wo = (const float*)d_in[7];
    const float* bo = (const float*)d_in[8];
    float* out = (float*)d_out;

    cudaFuncSetAttribute(phase1_hmma,
                         cudaFuncAttributeMaxDynamicSharedMemorySize, P1_SM);
    cudaFuncSetAttribute(lstm_hmma8,
                         cudaFuncAttributeMaxDynamicSharedMemorySize, SM_TOTAL2);

    reset_kernel<<<1, 1>>>();
    prep_x<<<(kT * kB * kIN) / 256, 256>>>(x);
    prep_wx<<<(4096 * kIN) / 256, 256>>>(Wf, Wi, Wc, Wo);
    prep_weights<<<NBLK, 256>>>(Wf, Wi, Wc, Wo);

    dim3 g1(4096 / 128, (kT * kB) / 128);   // 32 x 256
    phase1_hmma<<<g1, 512, P1_SM>>>(bf, bi, bc, bo);

    lstm_hmma8<<<NBLK, 512, SM_TOTAL2>>>(out);
}

// round 15
// speedup vs baseline: 2.1453x; 1.1835x over previous
#include <cuda_runtime.h>
#include <cuda_bf16.h>
#include <cuda_fp16.h>
#include <cstdint>

// ---------------------------------------------------------------------------
// LSTM T=512, B=64, IN=512, H=1024.
// Phase 1 (HMMA fp16 2-term): gx = x16 @ (Wx*2^10 hi/lo) / 2^10 + bias,
//   stored as fp16.
// Phase 2 (persistent, 128 CTAs x 512 thr): recurrent GEMM
//   h16 @ (Wh*2^10 fp16) single-term, fp32 accum, descale in epilogue.
//   16 warps = 4 m-tiles x 4 k-slices; chunk size 128k (8 chunks, 8 syncs);
//   cp.async ring-3 A staging; 4 pre partial buffers; c in registers;
//   split global barrier (release arrive + acquire poll).
// ---------------------------------------------------------------------------

static constexpr int kT  = 512;
static constexpr int kB  = 64;
static constexpr int kIN = 512;
static constexpr int kH  = 1024;
static constexpr int kBH = kB * kH;
static constexpr int NBLK = 128;
static constexpr float W_SCALE   = 1024.0f;
static constexpr float W_DESCALE = 1.0f / 1024.0f;

__device__ __half g_gx16[(size_t)kT * NBLK * kB * 32];    // [t][cta][b][vn] fp16
__device__ __half g_w16[(size_t)NBLK * 32768];            // per-CTA Wh (x2^10) fp16
__device__ __half g_h16[kB * kH];                         // h fp16 [b][k]
__device__ __half g_x16[(size_t)kT * kB * kIN];           // x fp16 [m][k]
__device__ __half g_wxhi[(size_t)4096 * kIN];             // Wx hi (x2^10) [n][k]
__device__ __half g_wxlo[(size_t)4096 * kIN];             // Wx lo (x2^10)
__device__ unsigned g_bar;

__device__ __forceinline__ uint32_t smem_u32(const void* p) {
    uint32_t a;
    asm("{ .reg .u64 t; cvta.to.shared.u64 t, %1; cvt.u32.u64 %0, t; }"
        : "=r"(a) : "l"(p));
    return a;
}
__device__ __forceinline__ void ldsm_x4(uint32_t* r, uint32_t addr) {
    asm volatile("ldmatrix.sync.aligned.m8n8.x4.shared.b16 {%0,%1,%2,%3}, [%4];"
                 : "=r"(r[0]), "=r"(r[1]), "=r"(r[2]), "=r"(r[3]) : "r"(addr));
}
__device__ __forceinline__ void mma_f16(float* c, const uint32_t* a,
                                        uint32_t b0, uint32_t b1) {
    asm volatile(
        "mma.sync.aligned.m16n8k16.row.col.f32.f16.f16.f32 "
        "{%0,%1,%2,%3}, {%4,%5,%6,%7}, {%8,%9}, {%0,%1,%2,%3};"
        : "+f"(c[0]), "+f"(c[1]), "+f"(c[2]), "+f"(c[3])
        : "r"(a[0]), "r"(a[1]), "r"(a[2]), "r"(a[3]), "r"(b0), "r"(b1));
}
__device__ __forceinline__ void cp16(uint32_t dst, const void* src) {
    asm volatile("cp.async.cg.shared.global [%0], [%1], 16;"
                 :: "r"(dst), "l"(src) : "memory");
}
__device__ __forceinline__ void cp_commit() {
    asm volatile("cp.async.commit_group;" ::: "memory");
}
__device__ __forceinline__ void cp_wait1() {
    asm volatile("cp.async.wait_group 1;" ::: "memory");
}
__device__ __forceinline__ void cp_wait0() {
    asm volatile("cp.async.wait_group 0;" ::: "memory");
}
__device__ __forceinline__ float sigmoidf_(float x) {
    return 1.0f / (1.0f + __expf(-x));
}
__device__ __forceinline__ void bar_arrive_release(unsigned* p) {
    asm volatile("red.release.gpu.global.add.u32 [%0], 1;" :: "l"(p) : "memory");
}
__device__ __forceinline__ unsigned ld_acquire(unsigned* p) {
    unsigned v;
    asm volatile("ld.acquire.gpu.global.u32 %0, [%1];" : "=r"(v) : "l"(p) : "memory");
    return v;
}

__global__ void reset_kernel() { g_bar = 0u; }

// ---------------------------------------------------------------------------
// Prep kernels
// ---------------------------------------------------------------------------
__global__ void __launch_bounds__(256) prep_x(const float* __restrict__ x) {
    size_t i = (size_t)blockIdx.x * 256 + threadIdx.x;
    g_x16[i] = __float2half_rn(x[i]);
}

__global__ void __launch_bounds__(256) prep_wx(
    const float* __restrict__ Wf, const float* __restrict__ Wi,
    const float* __restrict__ Wc, const float* __restrict__ Wo)
{
    size_t i = (size_t)blockIdx.x * 256 + threadIdx.x;   // 4096*512 total
    int n = (int)(i >> 9), k = (int)(i & 511);
    int gate = n >> 10, h = n & 1023;
    const float* W = (gate == 0) ? Wf : (gate == 1) ? Wi : (gate == 2) ? Wc : Wo;
    float v = W[(size_t)(kH + k) * kH + h] * W_SCALE;
    __half hi = __float2half_rn(v);
    __half lo = __float2half_rn(v - __half2float(hi));
    g_wxhi[i] = hi; g_wxlo[i] = lo;
}

__global__ void __launch_bounds__(256) prep_weights(
    const float* __restrict__ Wf, const float* __restrict__ Wi,
    const float* __restrict__ Wc, const float* __restrict__ Wo)
{
    const int cta = blockIdx.x;
    const int n0h = cta * 8;
    for (int g = 0; g < 4; g++) {
        const float* W = (g == 0) ? Wf : (g == 1) ? Wi : (g == 2) ? Wc : Wo;
        for (int idx = threadIdx.x; idx < 8 * kH; idx += 256) {
            int col = idx & 7, r = idx >> 3;
            float v = W[(size_t)r * kH + n0h + col] * W_SCALE;
            g_w16[(size_t)cta * 32768 + (size_t)(g * 8 + col) * kH + r] =
                __float2half_rn(v);
        }
    }
}

// ---------------------------------------------------------------------------
// Phase 1 HMMA (fp16 2-term): gx = X @ Wx + b.  M=32768, N=4096, K=512.
// Tile BM=128 x BN=128 x BK=64. 512 thr, 16 warps = 4 m32 x 4 n32.
// Epilogue stores fp16 gx.
// ---------------------------------------------------------------------------
static constexpr uint32_t P1_AB = 18432;   // 128 rows * 144 B
static constexpr uint32_t P1_OFFB = 2 * P1_AB;          // 36864
static constexpr uint32_t P1_SM = 6 * P1_AB;            // 110592

__global__ void __launch_bounds__(512, 1) phase1_hmma(
    const float* __restrict__ bf, const float* __restrict__ bi,
    const float* __restrict__ bc, const float* __restrict__ bo)
{
    extern __shared__ __align__(128) char smem[];
    const uint32_t sb = smem_u32(smem);
    const int tid  = threadIdx.x;
    const int wid  = tid >> 5;
    const int lane = tid & 31;
    const int mi2  = wid & 3;
    const int nw   = wid >> 2;
    const int n0   = blockIdx.x * 128;
    const int m0   = blockIdx.y * 128;
    const int gate = n0 >> 10;
    const float* biasg = (gate == 0) ? bf : (gate == 1) ? bi : (gate == 2) ? bc : bo;

    const int s_row0 = tid >> 3, s_c16 = tid & 7;
    const int s_row1 = (tid + 512) >> 3;
    const uint32_t so0 = (uint32_t)(s_row0 * 144 + s_c16 * 16);
    const uint32_t so1 = (uint32_t)(s_row1 * 144 + s_c16 * 16);

    auto stage = [&](int c) {
        const int buf = c & 1;
        const uint32_t a   = sb + buf * P1_AB;
        const uint32_t bhi = sb + P1_OFFB + buf * 2 * P1_AB;
        const uint32_t blo = bhi + P1_AB;
        const size_t ga0 = (size_t)(m0 + s_row0) * kIN + c * 64 + s_c16 * 8;
        const size_t ga1 = (size_t)(m0 + s_row1) * kIN + c * 64 + s_c16 * 8;
        const size_t gb0 = (size_t)(n0 + s_row0) * kIN + c * 64 + s_c16 * 8;
        const size_t gb1 = (size_t)(n0 + s_row1) * kIN + c * 64 + s_c16 * 8;
        cp16(a + so0, &g_x16[ga0]);    cp16(a + so1, &g_x16[ga1]);
        cp16(bhi + so0, &g_wxhi[gb0]); cp16(bhi + so1, &g_wxhi[gb1]);
        cp16(blo + so0, &g_wxlo[gb0]); cp16(blo + so1, &g_wxlo[gb1]);
    };

    uint32_t aoff[2];
#pragma unroll
    for (int i = 0; i < 2; i++)
        aoff[i] = (uint32_t)((32 * mi2 + 16 * i + (lane & 15)) * 144 + (lane >> 4) * 16);
    uint32_t boff[2];
#pragma unroll
    for (int j = 0; j < 2; j++)
        boff[j] = (uint32_t)((32 * nw + 16 * j + (lane & 7) + ((lane >> 4) << 3)) * 144
                             + ((lane >> 3) & 1) * 16);

    float C[2][2][2][4];
#pragma unroll
    for (int i = 0; i < 2; i++)
#pragma unroll
        for (int j = 0; j < 2; j++)
#pragma unroll
            for (int h2 = 0; h2 < 2; h2++)
#pragma unroll
                for (int q = 0; q < 4; q++) C[i][j][h2][q] = 0.0f;

    stage(0); cp_commit();

    for (int c = 0; c < 8; ++c) {
        if (c + 1 < 8) stage(c + 1);
        cp_commit();
        if (c + 1 < 8) cp_wait1(); else cp_wait0();
        __syncthreads();
        const int buf = c & 1;
        const uint32_t a   = sb + buf * P1_AB;
        const uint32_t bhi = sb + P1_OFFB + buf * 2 * P1_AB;
        const uint32_t blo = bhi + P1_AB;
#pragma unroll
        for (int u = 0; u < 4; ++u) {
            uint32_t ah[2][4], bh[2][4], bl[2][4];
#pragma unroll
            for (int i = 0; i < 2; i++)
                ldsm_x4(ah[i], a + aoff[i] + u * 32);
#pragma unroll
            for (int j = 0; j < 2; j++) {
                ldsm_x4(bh[j], bhi + boff[j] + u * 32);
                ldsm_x4(bl[j], blo + boff[j] + u * 32);
            }
#pragma unroll
            for (int i = 0; i < 2; i++)
#pragma unroll
                for (int j = 0; j < 2; j++) {
                    mma_f16(C[i][j][0], ah[i], bh[j][0], bh[j][1]);
                    mma_f16(C[i][j][1], ah[i], bh[j][2], bh[j][3]);
                    mma_f16(C[i][j][0], ah[i], bl[j][0], bl[j][1]);
                    mma_f16(C[i][j][1], ah[i], bl[j][2], bl[j][3]);
                }
        }
        __syncthreads();
    }

    // epilogue: descale + bias + scattered fp16 gx stores (half2, even offsets)
#pragma unroll
    for (int j = 0; j < 2; j++)
#pragma unroll
        for (int h2 = 0; h2 < 2; h2++) {
            const int col = 32 * nw + 16 * j + 8 * h2 + (lane & 3) * 2;
            const int n = n0 + col;
            const int hh = n & 1023;
            const int cta = hh >> 3, jj = hh & 7;
            const float b0 = biasg[hh], b1 = biasg[hh + 1];
#pragma unroll
            for (int i = 0; i < 2; i++)
#pragma unroll
                for (int rr = 0; rr < 2; rr++) {
                    const int r = 32 * mi2 + 16 * i + (lane >> 2) + 8 * rr;
                    const int m = m0 + r;
                    const int t = m >> 6, b = m & 63;
                    __half2 v = __floats2half2_rn(
                        C[i][j][h2][2 * rr]     * W_DESCALE + b0,
                        C[i][j][h2][2 * rr + 1] * W_DESCALE + b1);
                    *reinterpret_cast<__half2*>(
                        &g_gx16[(((size_t)t * NBLK + cta) * kB + b) * 32 + gate * 8 + jj]) = v;
                }
        }
}

// ---------------------------------------------------------------------------
// Persistent HMMA phase 2, v9 = R14 structure with 128k chunks (8 syncs).
// 128 CTAs x 512 threads. Warp w: mi = w&3 (m16), ks = w>>2.
// Warp ks handles k16 units {2ks, 2ks+1} of each 128k chunk.
// ---------------------------------------------------------------------------
static constexpr uint32_t SB_STRIDE = 2064;
static constexpr uint32_t OFF_BW  = 0;                           // 32 rows W
static constexpr uint32_t OFF_A   = 32 * SB_STRIDE;              // 66048
static constexpr uint32_t ABUF    = 64 * 272;                    // 17408 (128k chunk)
static constexpr int      PRE_STRIDE = 34;                       // floats (even)
static constexpr int      PRE_FLOATS = 64 * PRE_STRIDE;          // 2176
static constexpr uint32_t OFF_PRE = OFF_A + 3 * ABUF;            // 118272
static constexpr uint32_t SM_TOTAL2 = OFF_PRE + 4 * PRE_FLOATS * 4;  // 153088

__global__ void __launch_bounds__(512, 1) lstm_hmma9(float* __restrict__ out)
{
    extern __shared__ __align__(128) char smem[];
    const uint32_t sb = smem_u32(smem);

    const int tid  = threadIdx.x;
    const int wid  = tid >> 5;
    const int lane = tid & 31;
    const int bx   = blockIdx.x;
    const int n0h  = bx * 8;
    const int mi   = wid & 3;
    const int ks   = wid >> 2;

    // resident weights (single fp16 array)
    {
        const uint4* sw = reinterpret_cast<const uint4*>(&g_w16[(size_t)bx * 32768]);
        for (int i = tid; i < 4096; i += 512) {
            int n = i >> 7, c8 = i & 127;
            *reinterpret_cast<uint4*>(smem + OFF_BW + n * SB_STRIDE + c8 * 16) = sw[i];
        }
    }
    g_h16[bx * 512 + tid] = __float2half(0.0f);
    __syncthreads();
    if (tid == 0) {
        bar_arrive_release(&g_bar);
        while (ld_acquire(&g_bar) < NBLK) { __nanosleep(16); }
    }
    __syncthreads();

    // fragment bases: A rows stride 272 B; warp ks covers units 2ks, 2ks+1
    const uint32_t a_off = (uint32_t)((16 * mi + (lane & 15)) * 272
                                      + (lane >> 4) * 16 + ks * 64);
    uint32_t bW[2];
#pragma unroll
    for (int j = 0; j < 2; j++) {
        const uint32_t b_row = 16 * j + (lane & 7) + ((lane >> 4) << 3);
        bW[j] = sb + OFF_BW + b_row * SB_STRIDE + ((lane >> 3) & 1) * 16;
    }

    // staging: TWO 16B slots per thread (64 rows x 16 uint4 = 1024 slots)
    const int s_row0 = tid >> 4, s_c16 = tid & 15;   // rows 0..31
    const uint32_t so0 = (uint32_t)(s_row0 * 272 + s_c16 * 16);
    const uint32_t so1 = (uint32_t)((s_row0 + 32) * 272 + s_c16 * 16);

    // gate-update mapping
    const int ub = tid >> 3, uj = tid & 7;
    float* pre0 = reinterpret_cast<float*>(smem + OFF_PRE);
    float* pre1 = pre0 + PRE_FLOATS;
    float* pre2 = pre1 + PRE_FLOATS;
    float* pre3 = pre2 + PRE_FLOATS;
    float* preK = pre0 + ks * PRE_FLOATS;

    float c_reg = 0.0f;

    float gx4[4];
    {
        const __half* gx = &g_gx16[(((size_t)0 * NBLK + bx) * kB + ub) * 32];
#pragma unroll
        for (int g = 0; g < 4; ++g) gx4[g] = __half2float(gx[8 * g + uj]);
    }

    auto stageA = [&](int c) {
        const int buf = c % 3;
        const uint32_t abase = sb + OFF_A + buf * ABUF;
        const size_t g0 = (size_t)s_row0 * kH + c * 128 + s_c16 * 8;
        const size_t g1 = (size_t)(s_row0 + 32) * kH + c * 128 + s_c16 * 8;
        cp16(abase + so0, &g_h16[g0]);
        cp16(abase + so1, &g_h16[g1]);
    };

    for (int t = 0; t < kT; ++t) {
        float C00[4] = {0,0,0,0}, C01[4] = {0,0,0,0};
        float C10[4] = {0,0,0,0}, C11[4] = {0,0,0,0};

        stageA(0); cp_commit();
        stageA(1); cp_commit();

        for (int c = 0; c < 8; ++c) {       // 8 chunks of 128k
            cp_wait1();
            __syncthreads();
            if (c + 2 < 8) stageA(c + 2);
            cp_commit();

            const int buf = c % 3;
            const uint32_t abase = sb + OFF_A + buf * ABUF;
#pragma unroll
            for (int u = 0; u < 2; ++u) {
                uint32_t ah[4], bw0[4], bw1[4];
                ldsm_x4(ah, abase + a_off + u * 32);
                const uint32_t bo = (uint32_t)(c * 256 + ks * 64 + u * 32);
                ldsm_x4(bw0, bW[0] + bo);
                ldsm_x4(bw1, bW[1] + bo);
                mma_f16(C00, ah, bw0[0], bw0[1]); mma_f16(C01, ah, bw0[2], bw0[3]);
                mma_f16(C10, ah, bw1[0], bw1[1]); mma_f16(C11, ah, bw1[2], bw1[3]);
            }
        }

        // publish partials into pre[ks] (stride 34 -> float2 stores aligned)
        {
            const int r0 = 16 * mi + (lane >> 2);
            const int cb = (lane & 3) * 2;
            float2 v;
            v.x = C00[0]; v.y = C00[1];
            *reinterpret_cast<float2*>(&preK[r0 * PRE_STRIDE + cb]) = v;
            v.x = C00[2]; v.y = C00[3];
            *reinterpret_cast<float2*>(&preK[(r0 + 8) * PRE_STRIDE + cb]) = v;
            v.x = C01[0]; v.y = C01[1];
            *reinterpret_cast<float2*>(&preK[r0 * PRE_STRIDE + cb + 8]) = v;
            v.x = C01[2]; v.y = C01[3];
            *reinterpret_cast<float2*>(&preK[(r0 + 8) * PRE_STRIDE + cb + 8]) = v;
            v.x = C10[0]; v.y = C10[1];
            *reinterpret_cast<float2*>(&preK[r0 * PRE_STRIDE + cb + 16]) = v;
            v.x = C10[2]; v.y = C10[3];
            *reinterpret_cast<float2*>(&preK[(r0 + 8) * PRE_STRIDE + cb + 16]) = v;
            v.x = C11[0]; v.y = C11[1];
            *reinterpret_cast<float2*>(&preK[r0 * PRE_STRIDE + cb + 24]) = v;
            v.x = C11[2]; v.y = C11[3];
            *reinterpret_cast<float2*>(&preK[(r0 + 8) * PRE_STRIDE + cb + 24]) = v;
        }
        __syncthreads();

        // gate math + c/h update (1 item/thread); descale W by 2^-10
        {
            const int b = ub, j = uj;
            const int o0 = b * PRE_STRIDE + j;
            float pf = (pre0[o0]      + pre1[o0]      + pre2[o0]      + pre3[o0])      * W_DESCALE + gx4[0];
            float pi = (pre0[o0 + 8]  + pre1[o0 + 8]  + pre2[o0 + 8]  + pre3[o0 + 8])  * W_DESCALE + gx4[1];
            float pg = (pre0[o0 + 16] + pre1[o0 + 16] + pre2[o0 + 16] + pre3[o0 + 16]) * W_DESCALE + gx4[2];
            float po = (pre0[o0 + 24] + pre1[o0 + 24] + pre2[o0 + 24] + pre3[o0 + 24]) * W_DESCALE + gx4[3];
            float f  = sigmoidf_(pf);
            float ii = sigmoidf_(pi);
            float gg = tanhf(pg);
            float oo = sigmoidf_(po);
            float cn = f * c_reg + ii * gg;
            c_reg = cn;
            float h = oo * tanhf(cn);
            out[(size_t)t * kBH + (size_t)b * kH + n0h + j] = h;
            g_h16[b * kH + n0h + j] = __float2half_rn(h);
            if (t == kT - 1) {
                out[(size_t)kT * kBH + (size_t)b * kH + n0h + j] = h;
                out[(size_t)kT * kBH + kBH + (size_t)b * kH + n0h + j] = cn;
            }
        }

        // split global barrier (release arrive, gx prefetch, acquire wait)
        if (t < kT - 1) {
            __syncthreads();
            if (tid == 0) bar_arrive_release(&g_bar);
            {
                const __half* gx = &g_gx16[(((size_t)(t + 1) * NBLK + bx) * kB + ub) * 32];
#pragma unroll
                for (int g = 0; g < 4; ++g) gx4[g] = __half2float(gx[8 * g + uj]);
            }
            if (tid == 0) {
                const unsigned tgt = (unsigned)(t + 2) * NBLK;
                while (ld_acquire(&g_bar) < tgt) { __nanosleep(16); }
            }
            __syncthreads();
        }
    }
}

// ---------------------------------------------------------------------------
extern "C" void kernel_launch(void* const* d_in, const int* in_sizes, int n_in,
                              void* d_out, int out_size)
{
    const float* x  = (const float*)d_in[0];
    const float* Wf = (const float*)d_in[1];
    const float* bf = (const float*)d_in[2];
    const float* Wi = (const float*)d_in[3];
    const float* bi = (const float*)d_in[4];
    const float* Wc = (const float*)d_in[5];
    const float* bc = (const float*)d_in[6];
    const float* Wo = (const float*)d_in[7];
    const float* bo = (const float*)d_in[8];
    float* out = (float*)d_out;

    cudaFuncSetAttribute(phase1_hmma,
                         cudaFuncAttributeMaxDynamicSharedMemorySize, P1_SM);
    cudaFuncSetAttribute(lstm_hmma9,
                         cudaFuncAttributeMaxDynamicSharedMemorySize, SM_TOTAL2);

    reset_kernel<<<1, 1>>>();
    prep_x<<<(kT * kB * kIN) / 256, 256>>>(x);
    prep_wx<<<(4096 * kIN) / 256, 256>>>(Wf, Wi, Wc, Wo);
    prep_weights<<<NBLK, 256>>>(Wf, Wi, Wc, Wo);

    dim3 g1(4096 / 128, (kT * kB) / 128);   // 32 x 256
    phase1_hmma<<<g1, 512, P1_SM>>>(bf, bi, bc, bo);

    lstm_hmma9<<<NBLK, 512, SM_TOTAL2>>>(out);
}

// round 16
// speedup vs baseline: 2.2297x; 1.0393x over previous
#include <cuda_runtime.h>
#include <cuda_bf16.h>
#include <cuda_fp16.h>
#include <cstdint>

// ---------------------------------------------------------------------------
// LSTM T=512, B=64, IN=512, H=1024.
// Phase 1 (HMMA fp16 single-term): gx = x16 @ (Wx*2^10 fp16) / 2^10 + bias,
//   stored fp16.
// Phase 2 (persistent, 128 CTAs x 512 thr): recurrent GEMM
//   h16 @ (Wh*2^10 fp16) single-term, fp32 accum, descale in epilogue.
//   16 warps = 4 m-tiles x 4 k-slices; chunk size 256k (4 chunks, 8 syncs);
//   cp.async ring-3 A staging; 4 pre partial buffers; c in registers;
//   split global barrier (release arrive + acquire poll).
// ---------------------------------------------------------------------------

static constexpr int kT  = 512;
static constexpr int kB  = 64;
static constexpr int kIN = 512;
static constexpr int kH  = 1024;
static constexpr int kBH = kB * kH;
static constexpr int NBLK = 128;
static constexpr float W_SCALE   = 1024.0f;
static constexpr float W_DESCALE = 1.0f / 1024.0f;

__device__ __half g_gx16[(size_t)kT * NBLK * kB * 32];    // [t][cta][b][vn] fp16
__device__ __half g_w16[(size_t)NBLK * 32768];            // per-CTA Wh (x2^10) fp16
__device__ __half g_h16[kB * kH];                         // h fp16 [b][k]
__device__ __half g_x16[(size_t)kT * kB * kIN];           // x fp16 [m][k]
__device__ __half g_wx16[(size_t)4096 * kIN];             // Wx (x2^10) [n][k]
__device__ unsigned g_bar;

__device__ __forceinline__ uint32_t smem_u32(const void* p) {
    uint32_t a;
    asm("{ .reg .u64 t; cvta.to.shared.u64 t, %1; cvt.u32.u64 %0, t; }"
        : "=r"(a) : "l"(p));
    return a;
}
__device__ __forceinline__ void ldsm_x4(uint32_t* r, uint32_t addr) {
    asm volatile("ldmatrix.sync.aligned.m8n8.x4.shared.b16 {%0,%1,%2,%3}, [%4];"
                 : "=r"(r[0]), "=r"(r[1]), "=r"(r[2]), "=r"(r[3]) : "r"(addr));
}
__device__ __forceinline__ void mma_f16(float* c, const uint32_t* a,
                                        uint32_t b0, uint32_t b1) {
    asm volatile(
        "mma.sync.aligned.m16n8k16.row.col.f32.f16.f16.f32 "
        "{%0,%1,%2,%3}, {%4,%5,%6,%7}, {%8,%9}, {%0,%1,%2,%3};"
        : "+f"(c[0]), "+f"(c[1]), "+f"(c[2]), "+f"(c[3])
        : "r"(a[0]), "r"(a[1]), "r"(a[2]), "r"(a[3]), "r"(b0), "r"(b1));
}
__device__ __forceinline__ void cp16(uint32_t dst, const void* src) {
    asm volatile("cp.async.cg.shared.global [%0], [%1], 16;"
                 :: "r"(dst), "l"(src) : "memory");
}
__device__ __forceinline__ void cp_commit() {
    asm volatile("cp.async.commit_group;" ::: "memory");
}
__device__ __forceinline__ void cp_wait1() {
    asm volatile("cp.async.wait_group 1;" ::: "memory");
}
__device__ __forceinline__ void cp_wait0() {
    asm volatile("cp.async.wait_group 0;" ::: "memory");
}
__device__ __forceinline__ float sigmoidf_(float x) {
    return 1.0f / (1.0f + __expf(-x));
}
__device__ __forceinline__ void bar_arrive_release(unsigned* p) {
    asm volatile("red.release.gpu.global.add.u32 [%0], 1;" :: "l"(p) : "memory");
}
__device__ __forceinline__ unsigned ld_acquire(unsigned* p) {
    unsigned v;
    asm volatile("ld.acquire.gpu.global.u32 %0, [%1];" : "=r"(v) : "l"(p) : "memory");
    return v;
}

__global__ void reset_kernel() { g_bar = 0u; }

// ---------------------------------------------------------------------------
// Prep kernels
// ---------------------------------------------------------------------------
__global__ void __launch_bounds__(256) prep_x(const float* __restrict__ x) {
    size_t i = (size_t)blockIdx.x * 256 + threadIdx.x;
    g_x16[i] = __float2half_rn(x[i]);
}

__global__ void __launch_bounds__(256) prep_wx(
    const float* __restrict__ Wf, const float* __restrict__ Wi,
    const float* __restrict__ Wc, const float* __restrict__ Wo)
{
    size_t i = (size_t)blockIdx.x * 256 + threadIdx.x;   // 4096*512 total
    int n = (int)(i >> 9), k = (int)(i & 511);
    int gate = n >> 10, h = n & 1023;
    const float* W = (gate == 0) ? Wf : (gate == 1) ? Wi : (gate == 2) ? Wc : Wo;
    g_wx16[i] = __float2half_rn(W[(size_t)(kH + k) * kH + h] * W_SCALE);
}

__global__ void __launch_bounds__(256) prep_weights(
    const float* __restrict__ Wf, const float* __restrict__ Wi,
    const float* __restrict__ Wc, const float* __restrict__ Wo)
{
    const int cta = blockIdx.x;
    const int n0h = cta * 8;
    for (int g = 0; g < 4; g++) {
        const float* W = (g == 0) ? Wf : (g == 1) ? Wi : (g == 2) ? Wc : Wo;
        for (int idx = threadIdx.x; idx < 8 * kH; idx += 256) {
            int col = idx & 7, r = idx >> 3;
            float v = W[(size_t)r * kH + n0h + col] * W_SCALE;
            g_w16[(size_t)cta * 32768 + (size_t)(g * 8 + col) * kH + r] =
                __float2half_rn(v);
        }
    }
}

// ---------------------------------------------------------------------------
// Phase 1 HMMA (fp16 single-term): gx = X @ Wx + b.  M=32768, N=4096, K=512.
// Tile BM=128 x BN=128 x BK=64. 512 thr, 16 warps = 4 m32 x 4 n32.
// ---------------------------------------------------------------------------
static constexpr uint32_t P1_AB = 18432;   // 128 rows * 144 B
static constexpr uint32_t P1_OFFB = 2 * P1_AB;          // 36864 (A double buf)
static constexpr uint32_t P1_SM = 4 * P1_AB;            // 73728

__global__ void __launch_bounds__(512, 1) phase1_hmma(
    const float* __restrict__ bf, const float* __restrict__ bi,
    const float* __restrict__ bc, const float* __restrict__ bo)
{
    extern __shared__ __align__(128) char smem[];
    const uint32_t sb = smem_u32(smem);
    const int tid  = threadIdx.x;
    const int wid  = tid >> 5;
    const int lane = tid & 31;
    const int mi2  = wid & 3;
    const int nw   = wid >> 2;
    const int n0   = blockIdx.x * 128;
    const int m0   = blockIdx.y * 128;
    const int gate = n0 >> 10;
    const float* biasg = (gate == 0) ? bf : (gate == 1) ? bi : (gate == 2) ? bc : bo;

    const int s_row0 = tid >> 3, s_c16 = tid & 7;
    const int s_row1 = (tid + 512) >> 3;
    const uint32_t so0 = (uint32_t)(s_row0 * 144 + s_c16 * 16);
    const uint32_t so1 = (uint32_t)(s_row1 * 144 + s_c16 * 16);

    auto stage = [&](int c) {
        const int buf = c & 1;
        const uint32_t a  = sb + buf * P1_AB;
        const uint32_t bw = sb + P1_OFFB + buf * P1_AB;
        const size_t ga0 = (size_t)(m0 + s_row0) * kIN + c * 64 + s_c16 * 8;
        const size_t ga1 = (size_t)(m0 + s_row1) * kIN + c * 64 + s_c16 * 8;
        const size_t gb0 = (size_t)(n0 + s_row0) * kIN + c * 64 + s_c16 * 8;
        const size_t gb1 = (size_t)(n0 + s_row1) * kIN + c * 64 + s_c16 * 8;
        cp16(a + so0, &g_x16[ga0]);   cp16(a + so1, &g_x16[ga1]);
        cp16(bw + so0, &g_wx16[gb0]); cp16(bw + so1, &g_wx16[gb1]);
    };

    uint32_t aoff[2];
#pragma unroll
    for (int i = 0; i < 2; i++)
        aoff[i] = (uint32_t)((32 * mi2 + 16 * i + (lane & 15)) * 144 + (lane >> 4) * 16);
    uint32_t boff[2];
#pragma unroll
    for (int j = 0; j < 2; j++)
        boff[j] = (uint32_t)((32 * nw + 16 * j + (lane & 7) + ((lane >> 4) << 3)) * 144
                             + ((lane >> 3) & 1) * 16);

    float C[2][2][2][4];
#pragma unroll
    for (int i = 0; i < 2; i++)
#pragma unroll
        for (int j = 0; j < 2; j++)
#pragma unroll
            for (int h2 = 0; h2 < 2; h2++)
#pragma unroll
                for (int q = 0; q < 4; q++) C[i][j][h2][q] = 0.0f;

    stage(0); cp_commit();

    for (int c = 0; c < 8; ++c) {
        if (c + 1 < 8) stage(c + 1);
        cp_commit();
        if (c + 1 < 8) cp_wait1(); else cp_wait0();
        __syncthreads();
        const int buf = c & 1;
        const uint32_t a  = sb + buf * P1_AB;
        const uint32_t bw = sb + P1_OFFB + buf * P1_AB;
#pragma unroll
        for (int u = 0; u < 4; ++u) {
            uint32_t ah[2][4], bh[2][4];
#pragma unroll
            for (int i = 0; i < 2; i++)
                ldsm_x4(ah[i], a + aoff[i] + u * 32);
#pragma unroll
            for (int j = 0; j < 2; j++)
                ldsm_x4(bh[j], bw + boff[j] + u * 32);
#pragma unroll
            for (int i = 0; i < 2; i++)
#pragma unroll
                for (int j = 0; j < 2; j++) {
                    mma_f16(C[i][j][0], ah[i], bh[j][0], bh[j][1]);
                    mma_f16(C[i][j][1], ah[i], bh[j][2], bh[j][3]);
                }
        }
        __syncthreads();
    }

    // epilogue: descale + bias + scattered fp16 gx stores (half2, even offsets)
#pragma unroll
    for (int j = 0; j < 2; j++)
#pragma unroll
        for (int h2 = 0; h2 < 2; h2++) {
            const int col = 32 * nw + 16 * j + 8 * h2 + (lane & 3) * 2;
            const int n = n0 + col;
            const int hh = n & 1023;
            const int cta = hh >> 3, jj = hh & 7;
            const float b0 = biasg[hh], b1 = biasg[hh + 1];
#pragma unroll
            for (int i = 0; i < 2; i++)
#pragma unroll
                for (int rr = 0; rr < 2; rr++) {
                    const int r = 32 * mi2 + 16 * i + (lane >> 2) + 8 * rr;
                    const int m = m0 + r;
                    const int t = m >> 6, b = m & 63;
                    __half2 v = __floats2half2_rn(
                        C[i][j][h2][2 * rr]     * W_DESCALE + b0,
                        C[i][j][h2][2 * rr + 1] * W_DESCALE + b1);
                    *reinterpret_cast<__half2*>(
                        &g_gx16[(((size_t)t * NBLK + cta) * kB + b) * 32 + gate * 8 + jj]) = v;
                }
        }
}

// ---------------------------------------------------------------------------
// Persistent HMMA phase 2, v10 = R15 structure with 256k chunks (4 chunks).
// 128 CTAs x 512 threads. Warp w: mi = w&3 (m16), ks = w>>2.
// Warp ks handles k16 units {4ks..4ks+3} of each 256k chunk.
// A row stride 528 B (256 halves + 8 pad).
// ---------------------------------------------------------------------------
static constexpr uint32_t SB_STRIDE = 2064;
static constexpr uint32_t OFF_BW  = 0;                           // 32 rows W
static constexpr uint32_t OFF_A   = 32 * SB_STRIDE;              // 66048
static constexpr uint32_t A_RS    = 528;                         // bytes per A row
static constexpr uint32_t ABUF    = 64 * A_RS;                   // 33792
static constexpr int      PRE_STRIDE = 34;                       // floats (even)
static constexpr int      PRE_FLOATS = 64 * PRE_STRIDE;          // 2176
static constexpr uint32_t OFF_PRE = OFF_A + 3 * ABUF;            // 167424
static constexpr uint32_t SM_TOTAL2 = OFF_PRE + 4 * PRE_FLOATS * 4;  // 202240

__global__ void __launch_bounds__(512, 1) lstm_hmma10(float* __restrict__ out)
{
    extern __shared__ __align__(128) char smem[];
    const uint32_t sb = smem_u32(smem);

    const int tid  = threadIdx.x;
    const int wid  = tid >> 5;
    const int lane = tid & 31;
    const int bx   = blockIdx.x;
    const int n0h  = bx * 8;
    const int mi   = wid & 3;
    const int ks   = wid >> 2;

    // resident weights (single fp16 array)
    {
        const uint4* sw = reinterpret_cast<const uint4*>(&g_w16[(size_t)bx * 32768]);
        for (int i = tid; i < 4096; i += 512) {
            int n = i >> 7, c8 = i & 127;
            *reinterpret_cast<uint4*>(smem + OFF_BW + n * SB_STRIDE + c8 * 16) = sw[i];
        }
    }
    g_h16[bx * 512 + tid] = __float2half(0.0f);
    __syncthreads();
    if (tid == 0) {
        bar_arrive_release(&g_bar);
        while (ld_acquire(&g_bar) < NBLK) { __nanosleep(16); }
    }
    __syncthreads();

    // fragment bases: warp ks covers k16 units 4ks..4ks+3 of each 256k chunk
    const uint32_t a_off = (uint32_t)((16 * mi + (lane & 15)) * A_RS
                                      + (lane >> 4) * 16 + ks * 128);
    uint32_t bW[2];
#pragma unroll
    for (int j = 0; j < 2; j++) {
        const uint32_t b_row = 16 * j + (lane & 7) + ((lane >> 4) << 3);
        bW[j] = sb + OFF_BW + b_row * SB_STRIDE + ((lane >> 3) & 1) * 16;
    }

    // staging: FOUR 16B slots per thread (64 rows x 32 uint4 = 2048 slots)
    const int s_row0 = tid >> 3, s_c = tid & 7;   // rows 0..63, cols 0..7 (of 32)
    uint32_t so[4];
#pragma unroll
    for (int r = 0; r < 4; r++)
        so[r] = (uint32_t)(s_row0 * A_RS + (s_c + 8 * r) * 16);

    // gate-update mapping
    const int ub = tid >> 3, uj = tid & 7;
    float* pre0 = reinterpret_cast<float*>(smem + OFF_PRE);
    float* pre1 = pre0 + PRE_FLOATS;
    float* pre2 = pre1 + PRE_FLOATS;
    float* pre3 = pre2 + PRE_FLOATS;
    float* preK = pre0 + ks * PRE_FLOATS;

    float c_reg = 0.0f;

    float gx4[4];
    {
        const __half* gx = &g_gx16[(((size_t)0 * NBLK + bx) * kB + ub) * 32];
#pragma unroll
        for (int g = 0; g < 4; ++g) gx4[g] = __half2float(gx[8 * g + uj]);
    }

    auto stageA = [&](int c) {
        const int buf = c % 3;
        const uint32_t abase = sb + OFF_A + buf * ABUF;
        const size_t gb = (size_t)s_row0 * kH + c * 256;
#pragma unroll
        for (int r = 0; r < 4; r++)
            cp16(abase + so[r], &g_h16[gb + (s_c + 8 * r) * 8]);
    };

    for (int t = 0; t < kT; ++t) {
        float C00[4] = {0,0,0,0}, C01[4] = {0,0,0,0};
        float C10[4] = {0,0,0,0}, C11[4] = {0,0,0,0};

        stageA(0); cp_commit();
        stageA(1); cp_commit();

        for (int c = 0; c < 4; ++c) {       // 4 chunks of 256k
            cp_wait1();
            __syncthreads();
            if (c + 2 < 4) stageA(c + 2);
            cp_commit();

            const int buf = c % 3;
            const uint32_t abase = sb + OFF_A + buf * ABUF;
#pragma unroll
            for (int u = 0; u < 4; ++u) {
                uint32_t ah[4], bw0[4], bw1[4];
                ldsm_x4(ah, abase + a_off + u * 32);
                const uint32_t bo = (uint32_t)(c * 512 + ks * 128 + u * 32);
                ldsm_x4(bw0, bW[0] + bo);
                ldsm_x4(bw1, bW[1] + bo);
                mma_f16(C00, ah, bw0[0], bw0[1]); mma_f16(C01, ah, bw0[2], bw0[3]);
                mma_f16(C10, ah, bw1[0], bw1[1]); mma_f16(C11, ah, bw1[2], bw1[3]);
            }
        }

        // publish partials into pre[ks] (stride 34 -> float2 stores aligned)
        {
            const int r0 = 16 * mi + (lane >> 2);
            const int cb = (lane & 3) * 2;
            float2 v;
            v.x = C00[0]; v.y = C00[1];
            *reinterpret_cast<float2*>(&preK[r0 * PRE_STRIDE + cb]) = v;
            v.x = C00[2]; v.y = C00[3];
            *reinterpret_cast<float2*>(&preK[(r0 + 8) * PRE_STRIDE + cb]) = v;
            v.x = C01[0]; v.y = C01[1];
            *reinterpret_cast<float2*>(&preK[r0 * PRE_STRIDE + cb + 8]) = v;
            v.x = C01[2]; v.y = C01[3];
            *reinterpret_cast<float2*>(&preK[(r0 + 8) * PRE_STRIDE + cb + 8]) = v;
            v.x = C10[0]; v.y = C10[1];
            *reinterpret_cast<float2*>(&preK[r0 * PRE_STRIDE + cb + 16]) = v;
            v.x = C10[2]; v.y = C10[3];
            *reinterpret_cast<float2*>(&preK[(r0 + 8) * PRE_STRIDE + cb + 16]) = v;
            v.x = C11[0]; v.y = C11[1];
            *reinterpret_cast<float2*>(&preK[r0 * PRE_STRIDE + cb + 24]) = v;
            v.x = C11[2]; v.y = C11[3];
            *reinterpret_cast<float2*>(&preK[(r0 + 8) * PRE_STRIDE + cb + 24]) = v;
        }
        __syncthreads();

        // gate math + c/h update (1 item/thread); descale W by 2^-10
        {
            const int b = ub, j = uj;
            const int o0 = b * PRE_STRIDE + j;
            float pf = (pre0[o0]      + pre1[o0]      + pre2[o0]      + pre3[o0])      * W_DESCALE + gx4[0];
            float pi = (pre0[o0 + 8]  + pre1[o0 + 8]  + pre2[o0 + 8]  + pre3[o0 + 8])  * W_DESCALE + gx4[1];
            float pg = (pre0[o0 + 16] + pre1[o0 + 16] + pre2[o0 + 16] + pre3[o0 + 16]) * W_DESCALE + gx4[2];
            float po = (pre0[o0 + 24] + pre1[o0 + 24] + pre2[o0 + 24] + pre3[o0 + 24]) * W_DESCALE + gx4[3];
            float f  = sigmoidf_(pf);
            float ii = sigmoidf_(pi);
            float gg = tanhf(pg);
            float oo = sigmoidf_(po);
            float cn = f * c_reg + ii * gg;
            c_reg = cn;
            float h = oo * tanhf(cn);
            out[(size_t)t * kBH + (size_t)b * kH + n0h + j] = h;
            g_h16[b * kH + n0h + j] = __float2half_rn(h);
            if (t == kT - 1) {
                out[(size_t)kT * kBH + (size_t)b * kH + n0h + j] = h;
                out[(size_t)kT * kBH + kBH + (size_t)b * kH + n0h + j] = cn;
            }
        }

        // split global barrier (release arrive, gx prefetch, acquire wait)
        if (t < kT - 1) {
            __syncthreads();
            if (tid == 0) bar_arrive_release(&g_bar);
            {
                const __half* gx = &g_gx16[(((size_t)(t + 1) * NBLK + bx) * kB + ub) * 32];
#pragma unroll
                for (int g = 0; g < 4; ++g) gx4[g] = __half2float(gx[8 * g + uj]);
            }
            if (tid == 0) {
                const unsigned tgt = (unsigned)(t + 2) * NBLK;
                while (ld_acquire(&g_bar) < tgt) { __nanosleep(16); }
            }
            __syncthreads();
        }
    }
}

// ---------------------------------------------------------------------------
extern "C" void kernel_launch(void* const* d_in, const int* in_sizes, int n_in,
                              void* d_out, int out_size)
{
    const float* x  = (const float*)d_in[0];
    const float* Wf = (const float*)d_in[1];
    const float* bf = (const float*)d_in[2];
    const float* Wi = (const float*)d_in[3];
    const float* bi = (const float*)d_in[4];
    const float* Wc = (const float*)d_in[5];
    const float* bc = (const float*)d_in[6];
    const float* Wo = (const float*)d_in[7];
    const float* bo = (const float*)d_in[8];
    float* out = (float*)d_out;

    cudaFuncSetAttribute(phase1_hmma,
                         cudaFuncAttributeMaxDynamicSharedMemorySize, P1_SM);
    cudaFuncSetAttribute(lstm_hmma10,
                         cudaFuncAttributeMaxDynamicSharedMemorySize, SM_TOTAL2);

    reset_kernel<<<1, 1>>>();
    prep_x<<<(kT * kB * kIN) / 256, 256>>>(x);
    prep_wx<<<(4096 * kIN) / 256, 256>>>(Wf, Wi, Wc, Wo);
    prep_weights<<<NBLK, 256>>>(Wf, Wi, Wc, Wo);

    dim3 g1(4096 / 128, (kT * kB) / 128);   // 32 x 256
    phase1_hmma<<<g1, 512, P1_SM>>>(bf, bi, bc, bo);

    lstm_hmma10<<<NBLK, 512, SM_TOTAL2>>>(out);
}